// round 1
// baseline (speedup 1.0000x reference)
#include <cuda_runtime.h>
#include <math.h>

// Problem constants
#define BATCH 8          // 2N after concat
#define LSEQ  4096       // H*W
#define DMOD  256
#define DFF   512
#define NHEAD 8
#define HDIM  32
#define MROWS (BATCH * LSEQ)   // 32768

// ---------------- scratch (static device globals; no allocation) -------------
__device__ float g_x  [MROWS * DMOD];   // p1 (current)
__device__ float g_p2 [MROWS * DMOD];   // p2 (fixed across layers)
__device__ float g_q  [MROWS * DMOD];
__device__ float g_k  [MROWS * DMOD];
__device__ float g_v  [MROWS * DMOD];
__device__ float g_h  [MROWS * DFF];
__device__ float g_kv [BATCH * NHEAD * HDIM * HDIM];
__device__ float g_ks [BATCH * NHEAD * HDIM];

// ---------------- pos encoding + concat --------------------------------------
// p1 = concat(posenc(ref), posenc(src)); p2 = concat(posenc(src), posenc(ref))
// layout: [b][l][c], c contiguous.
__global__ void posenc_kernel(const float* __restrict__ ref,
                              const float* __restrict__ src,
                              float* __restrict__ p1, float* __restrict__ p2) {
    int c   = threadIdx.x;                 // 0..255
    int blk = blockIdx.x;                  // img*4*4096 + n*4096 + l
    int l   = blk & 4095;
    int n   = (blk >> 12) & 3;
    int img = blk >> 14;                   // 0 = ref, 1 = src

    int ii = c >> 2;
    int jj = c & 3;
    float dv  = expf(-(float)ii * (logf(10000.0f) / 64.0f));
    int   w   = l & 63, hh = l >> 6;
    float arg = (jj < 2 ? (float)w : (float)hh) * dv;
    float pe  = (jj & 1) ? cosf(arg) : sinf(arg);

    const float* inp = (img == 0) ? ref : src;
    float val = inp[((size_t)n * DMOD + c) * LSEQ + l] + pe;

    size_t o1 = ((size_t)(img * 4 + n) * LSEQ + l) * DMOD + c;
    size_t o2 = ((size_t)((1 - img) * 4 + n) * LSEQ + l) * DMOD + c;
    p1[o1] = val;
    p2[o2] = val;
}

// ---------------- SGEMM: C[M,N] = A[M,K] @ W[K,N] + bias, + activation -------
// act: 0 = none, 1 = elu(x)+1, 2 = relu
#define BM 128
#define BN 128
#define BK 16

__global__ __launch_bounds__(256)
void sgemm_bias(const float* __restrict__ A, const float* __restrict__ W,
                const float* __restrict__ bias, float* __restrict__ C,
                int M, int N, int K, int act) {
    __shared__ float As[BK][BM + 4];
    __shared__ float Bs[BK][BN + 4];

    int bm = blockIdx.y * BM;
    int bn = blockIdx.x * BN;
    int tid = threadIdx.x;
    int tx = tid & 15;        // 0..15 -> col groups of 8
    int ty = tid >> 4;        // 0..15 -> row groups of 8

    float acc[8][8];
#pragma unroll
    for (int i = 0; i < 8; i++)
#pragma unroll
        for (int j = 0; j < 8; j++) acc[i][j] = 0.0f;

    for (int k0 = 0; k0 < K; k0 += BK) {
        // load A tile 128x16 (row-major, K contiguous), store transposed
#pragma unroll
        for (int it = 0; it < 2; it++) {
            int f  = tid + it * 256;       // 0..511 float4 slots
            int r  = f >> 2;               // 0..127
            int kc = (f & 3) * 4;          // 0,4,8,12
            float4 vv = *(const float4*)(A + (size_t)(bm + r) * K + k0 + kc);
            As[kc + 0][r] = vv.x;
            As[kc + 1][r] = vv.y;
            As[kc + 2][r] = vv.z;
            As[kc + 3][r] = vv.w;
        }
        // load B tile 16x128 (row-major, N contiguous)
#pragma unroll
        for (int it = 0; it < 2; it++) {
            int f  = tid + it * 256;
            int r  = f >> 5;               // 0..15
            int cc = (f & 31) * 4;         // 0..124
            *(float4*)&Bs[r][cc] = *(const float4*)(W + (size_t)(k0 + r) * N + bn + cc);
        }
        __syncthreads();

#pragma unroll
        for (int kk = 0; kk < BK; kk++) {
            float a[8], b[8];
            *(float4*)(a)     = *(float4*)&As[kk][ty * 8];
            *(float4*)(a + 4) = *(float4*)&As[kk][ty * 8 + 4];
            *(float4*)(b)     = *(float4*)&Bs[kk][tx * 8];
            *(float4*)(b + 4) = *(float4*)&Bs[kk][tx * 8 + 4];
#pragma unroll
            for (int i = 0; i < 8; i++)
#pragma unroll
                for (int j = 0; j < 8; j++)
                    acc[i][j] = fmaf(a[i], b[j], acc[i][j]);
        }
        __syncthreads();
    }

    // epilogue
    float bv[8];
#pragma unroll
    for (int j = 0; j < 8; j++) bv[j] = bias[bn + tx * 8 + j];

#pragma unroll
    for (int i = 0; i < 8; i++) {
        size_t row = (size_t)(bm + ty * 8 + i);
        float* cp = C + row * N + bn + tx * 8;
        float out[8];
#pragma unroll
        for (int j = 0; j < 8; j++) {
            float v = acc[i][j] + bv[j];
            if (act == 1) v = (v > 0.0f) ? (v + 1.0f) : expf(v);   // elu(v)+1
            else if (act == 2) v = fmaxf(v, 0.0f);                 // relu
            out[j] = v;
        }
        *(float4*)(cp)     = *(float4*)(out);
        *(float4*)(cp + 4) = *(float4*)(out + 4);
    }
}

// ---------------- KV reduction: per (b,h) KV[m][d] = sum_l V[l,m]*K[l,d] -----
__global__ void kv_reduce(const float* __restrict__ Kin, const float* __restrict__ Vin,
                          float* __restrict__ KV, float* __restrict__ Ksum) {
    int bh = blockIdx.x;          // 0..63
    int b  = bh >> 3;
    int h  = bh & 7;
    int tid = threadIdx.x;        // 256

    __shared__ float Ks[32][36];  // pad to 36 for float4 alignment + banks
    __shared__ float Vs[32][32];

    int m  = tid >> 3;            // 0..31
    int d0 = (tid & 7) * 4;       // 0..28

    float acc[4] = {0.f, 0.f, 0.f, 0.f};
    float ks[4]  = {0.f, 0.f, 0.f, 0.f};

    int lr = tid >> 3;            // loader row 0..31
    int lc = (tid & 7) * 4;       // loader col

    for (int l0 = 0; l0 < LSEQ; l0 += 32) {
        size_t base = ((size_t)(b * LSEQ + l0 + lr)) * DMOD + h * HDIM + lc;
        float4 kv4 = *(const float4*)(Kin + base);
        float4 vv4 = *(const float4*)(Vin + base);
        Ks[lr][lc + 0] = kv4.x; Ks[lr][lc + 1] = kv4.y;
        Ks[lr][lc + 2] = kv4.z; Ks[lr][lc + 3] = kv4.w;
        *(float4*)&Vs[lr][lc] = vv4;
        __syncthreads();

#pragma unroll 8
        for (int r = 0; r < 32; r++) {
            float vm = Vs[r][m];
#pragma unroll
            for (int j = 0; j < 4; j++)
                acc[j] = fmaf(vm, Ks[r][d0 + j], acc[j]);
            if (m == 0) {
#pragma unroll
                for (int j = 0; j < 4; j++) ks[j] += Ks[r][d0 + j];
            }
        }
        __syncthreads();
    }

#pragma unroll
    for (int j = 0; j < 4; j++)
        KV[((size_t)bh * HDIM + m) * HDIM + d0 + j] = acc[j];
    if (m == 0) {
#pragma unroll
        for (int j = 0; j < 4; j++) Ksum[bh * HDIM + d0 + j] = ks[j];
    }
}

// ---------------- attention apply: out[l,h,m] = z * sum_d Q[l,h,d]*KV[h,m,d] -
__global__ void attn_apply(const float* __restrict__ Q, const float* __restrict__ KV,
                           const float* __restrict__ Ksum, float* __restrict__ Out) {
    int blk = blockIdx.x;          // b*32 + tile
    int b   = blk >> 5;
    int lt  = (blk & 31) * 128;
    int tid = threadIdx.x;         // 256 -> one output channel

    __shared__ float KVs[NHEAD * HDIM * 33];
    __shared__ float Ksums[NHEAD * HDIM];

    for (int i = tid; i < NHEAD * HDIM * HDIM; i += 256) {
        int h = i >> 10, m = (i >> 5) & 31, d = i & 31;
        KVs[(h * HDIM + m) * 33 + d] = KV[((size_t)(b * NHEAD + h) * HDIM + m) * HDIM + d];
    }
    for (int i = tid; i < NHEAD * HDIM; i += 256)
        Ksums[i] = Ksum[b * NHEAD * HDIM + i];
    __syncthreads();

    int h = tid >> 5, m = tid & 31;
    const float* kvrow = &KVs[(h * HDIM + m) * 33];
    const float* ksr   = &Ksums[h * HDIM];

    for (int r = 0; r < 128; r++) {
        int l = lt + r;
        const float* q = Q + ((size_t)(b * LSEQ + l)) * DMOD + h * HDIM;
        float num = 0.f, den = 0.f;
#pragma unroll
        for (int d = 0; d < HDIM; d += 4) {
            float4 qv = *(const float4*)(q + d);
            num = fmaf(qv.x, kvrow[d],     num);
            num = fmaf(qv.y, kvrow[d + 1], num);
            num = fmaf(qv.z, kvrow[d + 2], num);
            num = fmaf(qv.w, kvrow[d + 3], num);
            den = fmaf(qv.x, ksr[d],     den);
            den = fmaf(qv.y, ksr[d + 1], den);
            den = fmaf(qv.z, ksr[d + 2], den);
            den = fmaf(qv.w, ksr[d + 3], den);
        }
        Out[((size_t)(b * LSEQ + l)) * DMOD + tid] = num / (den + 1e-6f);
    }
}

// ---------------- fused residual-add + LayerNorm (warp per row) --------------
__global__ void ln_add(const float* __restrict__ A, const float* __restrict__ Bt,
                       const float* __restrict__ gamma, const float* __restrict__ beta,
                       float* __restrict__ Out) {
    int row  = blockIdx.x * 8 + (threadIdx.x >> 5);
    int lane = threadIdx.x & 31;
    const float* a  = A  + (size_t)row * DMOD;
    const float* bb = Bt + (size_t)row * DMOD;

    int c0 = lane * 4, c1 = 128 + lane * 4;
    float4 x0 = *(const float4*)(a + c0);
    float4 x1 = *(const float4*)(a + c1);
    float4 y0 = *(const float4*)(bb + c0);
    float4 y1 = *(const float4*)(bb + c1);

    float v[8];
    v[0] = x0.x + y0.x; v[1] = x0.y + y0.y; v[2] = x0.z + y0.z; v[3] = x0.w + y0.w;
    v[4] = x1.x + y1.x; v[5] = x1.y + y1.y; v[6] = x1.z + y1.z; v[7] = x1.w + y1.w;

    float s = 0.f;
#pragma unroll
    for (int i = 0; i < 8; i++) s += v[i];
#pragma unroll
    for (int o = 16; o > 0; o >>= 1) s += __shfl_xor_sync(0xffffffffu, s, o);
    float mean = s * (1.0f / 256.0f);

    float q = 0.f;
#pragma unroll
    for (int i = 0; i < 8; i++) { float d = v[i] - mean; q += d * d; }
#pragma unroll
    for (int o = 16; o > 0; o >>= 1) q += __shfl_xor_sync(0xffffffffu, q, o);
    float inv = rsqrtf(q * (1.0f / 256.0f) + 1e-5f);

    float* op = Out + (size_t)row * DMOD;
    float o8[8];
#pragma unroll
    for (int i = 0; i < 4; i++)
        o8[i] = (v[i] - mean) * inv * gamma[c0 + i] + beta[c0 + i];
#pragma unroll
    for (int i = 0; i < 4; i++)
        o8[4 + i] = (v[4 + i] - mean) * inv * gamma[c1 + i] + beta[c1 + i];
    *(float4*)(op + c0) = *(float4*)(o8);
    *(float4*)(op + c1) = *(float4*)(o8 + 4);
}

// ---------------- output writeback: out[n][c][l] = X[n][l][c] -----------------
__global__ void write_out(const float* __restrict__ X, float* __restrict__ out) {
    size_t i = (size_t)blockIdx.x * 256 + threadIdx.x;   // n,c,l with l fastest
    int n = (int)(i >> 20);
    int c = (int)((i >> 12) & 255);
    int l = (int)(i & 4095);
    out[i] = X[((size_t)n * LSEQ + l) * DMOD + c];
}

// ---------------- host orchestration -----------------------------------------
extern "C" void kernel_launch(void* const* d_in, const int* in_sizes, int n_in,
                              void* d_out, int out_size) {
    const float* ref = (const float*)d_in[0];
    const float* src = (const float*)d_in[1];
    const float* Wq  = (const float*)d_in[2];
    const float* bq  = (const float*)d_in[3];
    const float* Wk  = (const float*)d_in[4];
    const float* bk  = (const float*)d_in[5];
    const float* Wv  = (const float*)d_in[6];
    const float* bv  = (const float*)d_in[7];
    const float* Wo  = (const float*)d_in[8];
    const float* bo  = (const float*)d_in[9];
    const float* W1  = (const float*)d_in[10];
    const float* b1  = (const float*)d_in[11];
    const float* W2  = (const float*)d_in[12];
    const float* b2  = (const float*)d_in[13];
    const float* G1  = (const float*)d_in[14];
    const float* Be1 = (const float*)d_in[15];
    const float* G2  = (const float*)d_in[16];
    const float* Be2 = (const float*)d_in[17];

    float *x, *p2, *q, *k, *v, *h, *kv, *ks;
    cudaGetSymbolAddress((void**)&x,  g_x);
    cudaGetSymbolAddress((void**)&p2, g_p2);
    cudaGetSymbolAddress((void**)&q,  g_q);
    cudaGetSymbolAddress((void**)&k,  g_k);
    cudaGetSymbolAddress((void**)&v,  g_v);
    cudaGetSymbolAddress((void**)&h,  g_h);
    cudaGetSymbolAddress((void**)&kv, g_kv);
    cudaGetSymbolAddress((void**)&ks, g_ks);

    posenc_kernel<<<2 * 4 * LSEQ, 256>>>(ref, src, x, p2);

    dim3 grid256(DMOD / BN, MROWS / BM);   // (2, 256)
    dim3 grid512(DFF  / BN, MROWS / BM);   // (4, 256)

    for (int li = 0; li < 4; li++) {
        const float* s = (li % 2 == 0) ? x : p2;   // self / cross
        size_t wo  = (size_t)li * DMOD * DMOD;
        size_t bo_ = (size_t)li * DMOD;
        size_t w1o = (size_t)li * DMOD * DFF;
        size_t w2o = (size_t)li * DFF * DMOD;
        size_t b1o = (size_t)li * DFF;

        sgemm_bias<<<grid256, 256>>>(x, Wq + wo, bq + bo_, q, MROWS, DMOD, DMOD, 1);
        sgemm_bias<<<grid256, 256>>>(s, Wk + wo, bk + bo_, k, MROWS, DMOD, DMOD, 1);
        sgemm_bias<<<grid256, 256>>>(s, Wv + wo, bv + bo_, v, MROWS, DMOD, DMOD, 0);

        kv_reduce<<<BATCH * NHEAD, 256>>>(k, v, kv, ks);
        attn_apply<<<BATCH * 32, 256>>>(q, kv, ks, k);   // msg -> k buffer

        sgemm_bias<<<grid256, 256>>>(k, Wo + wo, bo + bo_, v, MROWS, DMOD, DMOD, 0);
        ln_add<<<MROWS / 8, 256>>>(x, v, G1 + bo_, Be1 + bo_, x);

        sgemm_bias<<<grid512, 256>>>(x, W1 + w1o, b1 + b1o, h, MROWS, DFF, DMOD, 2);
        sgemm_bias<<<grid256, 256>>>(h, W2 + w2o, b2 + bo_, q, MROWS, DMOD, DFF, 0);
        ln_add<<<MROWS / 8, 256>>>(x, q, G2 + bo_, Be2 + bo_, x);
    }

    write_out<<<(MROWS * DMOD) / 256, 256>>>(x, (float*)d_out);
}

// round 2
// speedup vs baseline: 1.1303x; 1.1303x over previous
#include <cuda_runtime.h>
#include <math.h>
#include <stdint.h>

// Problem constants
#define BATCH 8          // 2N after concat
#define LSEQ  4096       // H*W
#define DMOD  256
#define DFF   512
#define NHEAD 8
#define HDIM  32
#define MROWS (BATCH * LSEQ)   // 32768
#define KVCH  16               // L-chunks for kv partial reduction

// ---------------- scratch (static device globals; no allocation) -------------
__device__ float g_x  [MROWS * DMOD];   // p1 (current)
__device__ float g_p2 [MROWS * DMOD];   // p2 (fixed across layers)
__device__ float g_q  [MROWS * DMOD];
__device__ float g_k  [MROWS * DMOD];
__device__ float g_v  [MROWS * DMOD];
__device__ float g_h  [MROWS * DFF];
__device__ float g_kv [BATCH * NHEAD * HDIM * HDIM];
__device__ float g_ks [BATCH * NHEAD * HDIM];
__device__ float g_kvp[BATCH * NHEAD * KVCH * HDIM * HDIM];
__device__ float g_ksp[BATCH * NHEAD * KVCH * HDIM];

// ---------------- helpers -----------------------------------------------------
__device__ __forceinline__ uint32_t f2tf32(float x) {
    uint32_t y;
    asm("cvt.rna.tf32.f32 %0, %1;" : "=r"(y) : "f"(x));
    return y;
}

__device__ __forceinline__ void mma_tf32(float* acc, const uint32_t* a, const uint32_t* b) {
    asm volatile(
        "mma.sync.aligned.m16n8k8.row.col.f32.tf32.tf32.f32 "
        "{%0,%1,%2,%3}, {%4,%5,%6,%7}, {%8,%9}, {%0,%1,%2,%3};\n"
        : "+f"(acc[0]), "+f"(acc[1]), "+f"(acc[2]), "+f"(acc[3])
        : "r"(a[0]), "r"(a[1]), "r"(a[2]), "r"(a[3]), "r"(b[0]), "r"(b[1]));
}

// ---------------- pos encoding + concat (transpose through smem) --------------
// input: [img][n][c][l] ; outputs p1/p2: [b][l][c]
// grid: (img, n, ctile(8) * ltile(128)); block 256
__global__ void posenc_kernel(const float* __restrict__ ref,
                              const float* __restrict__ src,
                              float* __restrict__ p1, float* __restrict__ p2) {
    __shared__ float s[32][33];
    int img = blockIdx.y >> 2;
    int n   = blockIdx.y & 3;
    int ct  = blockIdx.x >> 7;        // 0..7
    int lt  = blockIdx.x & 127;       // 0..127
    int c0  = ct * 32, l0 = lt * 32;
    int tid = threadIdx.x;

    const float* inp = (img == 0) ? ref : src;

    // load: lanes over l (coalesced), rows over c
#pragma unroll
    for (int p = 0; p < 4; p++) {
        int c = p * 8 + (tid >> 5);
        int l = tid & 31;
        s[c][l] = inp[((size_t)n * DMOD + c0 + c) * LSEQ + l0 + l];
    }
    __syncthreads();

    // write: lanes over c (coalesced), rows over l; add pe computed per (c,l)
#pragma unroll
    for (int p = 0; p < 4; p++) {
        int l = p * 8 + (tid >> 5);
        int c = tid & 31;
        int cg = c0 + c, lg = l0 + l;
        int ii = cg >> 2, jj = cg & 3;
        float dv  = __expf(-(float)ii * (logf(10000.0f) / 64.0f));
        int   w   = lg & 63, hh = lg >> 6;
        float arg = (jj < 2 ? (float)w : (float)hh) * dv;
        float pe  = (jj & 1) ? cosf(arg) : sinf(arg);
        float val = s[c][l] + pe;
        size_t o1 = ((size_t)(img * 4 + n) * LSEQ + lg) * DMOD + cg;
        size_t o2 = ((size_t)((1 - img) * 4 + n) * LSEQ + lg) * DMOD + cg;
        p1[o1] = val;
        p2[o2] = val;
    }
}

// ---------------- TF32 tensor-core GEMM --------------------------------------
// C[M,N] = A[M,K] @ W[K,N] + bias, + activation (0 none, 1 elu+1, 2 relu)
// Block tile 128x128x32, 256 threads = 8 warps, warp tile 64x32.
// Shared memory holds fragment-prepacked tf32 tiles.
#define BM 128
#define BN 128
#define BK 32

__global__ __launch_bounds__(256)
void gemm_tf32(const float* __restrict__ A, const float* __restrict__ W,
               const float* __restrict__ bias, float* __restrict__ C,
               int M, int N, int K, int act) {
    // A frag layout: [kc(4)][mt(8)][t(32)][r(4)]  -> 4096 u32 = 16KB
    // B frag layout: [kc(4)][nt(16)][t(32)][r(2)] -> 4096 u32 = 16KB
    __shared__ uint32_t As[4096];
    __shared__ uint32_t Bs[4096];

    int bm = blockIdx.y * BM;
    int bn = blockIdx.x * BN;
    int tid  = threadIdx.x;
    int lane = tid & 31;
    int warp = tid >> 5;
    int wm = warp >> 2;          // 0..1 (m)
    int wn = warp & 3;           // 0..3 (n)
    int g  = lane >> 2;          // 0..7
    int t4 = lane & 3;           // 0..3

    float acc[4][4][4];
#pragma unroll
    for (int i = 0; i < 4; i++)
#pragma unroll
        for (int j = 0; j < 4; j++)
#pragma unroll
            for (int r = 0; r < 4; r++) acc[i][j][r] = 0.0f;

    for (int k0 = 0; k0 < K; k0 += BK) {
        // ---- load A tile 128x32 into fragment layout ----
#pragma unroll
        for (int it = 0; it < 4; it++) {
            int f = tid + it * 256;            // 0..1023 float4 slots
            int row = f >> 3;                  // 0..127
            int kbase = (f & 7) * 4;           // 0..28
            float4 v = *(const float4*)(A + (size_t)(bm + row) * K + k0 + kbase);
            float e[4] = {v.x, v.y, v.z, v.w};
            int mt = row >> 4;
            int rr = row & 15;
#pragma unroll
            for (int q = 0; q < 4; q++) {
                int k  = kbase + q;
                int kc = k >> 3, col = k & 7;
                int t  = ((rr & 7) << 2) | (col & 3);
                int r  = (rr >> 3) | ((col >> 2) << 1);
                As[((((kc << 3) + mt) << 5) + t) * 4 + r] = f2tf32(e[q]);
            }
        }
        // ---- load B tile 32x128 into fragment layout ----
#pragma unroll
        for (int it = 0; it < 4; it++) {
            int f = tid + it * 256;
            int krow = f >> 5;                 // 0..31
            int ncol = (f & 31) * 4;           // 0..124
            float4 v = *(const float4*)(W + (size_t)(k0 + krow) * N + bn + ncol);
            float e[4] = {v.x, v.y, v.z, v.w};
            int kc = krow >> 3, kr = krow & 7;
            int t4b = kr & 3, rb = kr >> 2;
#pragma unroll
            for (int q = 0; q < 4; q++) {
                int n  = ncol + q;
                int nt = n >> 3, gb = n & 7;
                int t  = (gb << 2) | t4b;
                Bs[((((kc << 4) + nt) << 5) + t) * 2 + rb] = f2tf32(e[q]);
            }
        }
        __syncthreads();

#pragma unroll
        for (int kc = 0; kc < 4; kc++) {
            uint32_t a[4][4], b[4][2];
#pragma unroll
            for (int i = 0; i < 4; i++) {
                int mt = wm * 4 + i;
                uint4 va = *(const uint4*)&As[((((kc << 3) + mt) << 5) + lane) * 4];
                a[i][0] = va.x; a[i][1] = va.y; a[i][2] = va.z; a[i][3] = va.w;
            }
#pragma unroll
            for (int j = 0; j < 4; j++) {
                int nt = wn * 4 + j;
                uint2 vb = *(const uint2*)&Bs[((((kc << 4) + nt) << 5) + lane) * 2];
                b[j][0] = vb.x; b[j][1] = vb.y;
            }
#pragma unroll
            for (int i = 0; i < 4; i++)
#pragma unroll
                for (int j = 0; j < 4; j++)
                    mma_tf32(acc[i][j], a[i], b[j]);
        }
        __syncthreads();
    }

    // ---- epilogue: bias + activation, float2 stores ----
#pragma unroll
    for (int j = 0; j < 4; j++) {
        int col = bn + wn * 32 + j * 8 + t4 * 2;
        float2 bv = *(const float2*)(bias + col);
#pragma unroll
        for (int i = 0; i < 4; i++) {
            int row0 = bm + wm * 64 + i * 16 + g;
#pragma unroll
            for (int half = 0; half < 2; half++) {
                int row = row0 + half * 8;
                float v0 = acc[i][j][half * 2 + 0] + bv.x;
                float v1 = acc[i][j][half * 2 + 1] + bv.y;
                if (act == 1) {
                    v0 = (v0 > 0.0f) ? (v0 + 1.0f) : __expf(v0);
                    v1 = (v1 > 0.0f) ? (v1 + 1.0f) : __expf(v1);
                } else if (act == 2) {
                    v0 = fmaxf(v0, 0.0f);
                    v1 = fmaxf(v1, 0.0f);
                }
                float2 out = make_float2(v0, v1);
                *(float2*)(C + (size_t)row * N + col) = out;
            }
        }
    }
}

// ---------------- KV partial reduction (stage 1) ------------------------------
// grid: 64*KVCH blocks; each computes partial KV over 256 rows of L.
__global__ void kv_partial(const float* __restrict__ Kin, const float* __restrict__ Vin,
                           float* __restrict__ KVp, float* __restrict__ Ksp) {
    int blk = blockIdx.x;
    int bh = blk >> 4;            // 0..63
    int ch = blk & (KVCH - 1);    // 0..15
    int b  = bh >> 3;
    int h  = bh & 7;
    int tid = threadIdx.x;        // 256

    __shared__ float Ks[32][36];
    __shared__ float Vs[32][32];

    int m  = tid >> 3;            // 0..31
    int d0 = (tid & 7) * 4;       // 0..28

    float acc[4] = {0.f, 0.f, 0.f, 0.f};
    float ks[4]  = {0.f, 0.f, 0.f, 0.f};

    int lr = tid >> 3;
    int lc = (tid & 7) * 4;

    int lbeg = ch * (LSEQ / KVCH);
    int lend = lbeg + (LSEQ / KVCH);
    for (int l0 = lbeg; l0 < lend; l0 += 32) {
        size_t base = ((size_t)(b * LSEQ + l0 + lr)) * DMOD + h * HDIM + lc;
        float4 kv4 = *(const float4*)(Kin + base);
        float4 vv4 = *(const float4*)(Vin + base);
        Ks[lr][lc + 0] = kv4.x; Ks[lr][lc + 1] = kv4.y;
        Ks[lr][lc + 2] = kv4.z; Ks[lr][lc + 3] = kv4.w;
        *(float4*)&Vs[lr][lc] = vv4;
        __syncthreads();

#pragma unroll 8
        for (int r = 0; r < 32; r++) {
            float vm = Vs[r][m];
#pragma unroll
            for (int j = 0; j < 4; j++)
                acc[j] = fmaf(vm, Ks[r][d0 + j], acc[j]);
            if (m == 0) {
#pragma unroll
                for (int j = 0; j < 4; j++) ks[j] += Ks[r][d0 + j];
            }
        }
        __syncthreads();
    }

    size_t obase = ((size_t)blk * HDIM + m) * HDIM + d0;
#pragma unroll
    for (int j = 0; j < 4; j++) KVp[obase + j] = acc[j];
    if (m == 0) {
#pragma unroll
        for (int j = 0; j < 4; j++) Ksp[blk * HDIM + d0 + j] = ks[j];
    }
}

// ---------------- KV finalize (stage 2) ---------------------------------------
__global__ void kv_finalize(const float* __restrict__ KVp, const float* __restrict__ Ksp,
                            float* __restrict__ KV, float* __restrict__ Ksum) {
    int bh = blockIdx.x;
    int tid = threadIdx.x;
#pragma unroll
    for (int o = 0; o < 4; o++) {
        int idx = tid + o * 256;          // 0..1023 (m*32+d)
        float s = 0.f;
#pragma unroll
        for (int c = 0; c < KVCH; c++)
            s += KVp[((size_t)(bh * KVCH + c)) * (HDIM * HDIM) + idx];
        KV[(size_t)bh * (HDIM * HDIM) + idx] = s;
    }
    if (tid < HDIM) {
        float s = 0.f;
#pragma unroll
        for (int c = 0; c < KVCH; c++)
            s += Ksp[(bh * KVCH + c) * HDIM + tid];
        Ksum[bh * HDIM + tid] = s;
    }
}

// ---------------- attention apply ---------------------------------------------
__global__ void attn_apply(const float* __restrict__ Q, const float* __restrict__ KV,
                           const float* __restrict__ Ksum, float* __restrict__ Out) {
    int blk = blockIdx.x;          // b*32 + tile
    int b   = blk >> 5;
    int lt  = (blk & 31) * 128;
    int tid = threadIdx.x;         // 256 -> one output channel

    __shared__ float KVs[NHEAD * HDIM * 33];
    __shared__ float Ksums[NHEAD * HDIM];

    for (int i = tid; i < NHEAD * HDIM * HDIM; i += 256) {
        int h = i >> 10, m = (i >> 5) & 31, d = i & 31;
        KVs[(h * HDIM + m) * 33 + d] = KV[((size_t)(b * NHEAD + h) * HDIM + m) * HDIM + d];
    }
    for (int i = tid; i < NHEAD * HDIM; i += 256)
        Ksums[i] = Ksum[b * NHEAD * HDIM + i];
    __syncthreads();

    int h = tid >> 5, m = tid & 31;
    const float* kvrow = &KVs[(h * HDIM + m) * 33];
    const float* ksr   = &Ksums[h * HDIM];

    for (int r = 0; r < 128; r++) {
        int l = lt + r;
        const float* q = Q + ((size_t)(b * LSEQ + l)) * DMOD + h * HDIM;
        float num = 0.f, den = 0.f;
#pragma unroll
        for (int d = 0; d < HDIM; d += 4) {
            float4 qv = *(const float4*)(q + d);
            num = fmaf(qv.x, kvrow[d],     num);
            num = fmaf(qv.y, kvrow[d + 1], num);
            num = fmaf(qv.z, kvrow[d + 2], num);
            num = fmaf(qv.w, kvrow[d + 3], num);
            den = fmaf(qv.x, ksr[d],     den);
            den = fmaf(qv.y, ksr[d + 1], den);
            den = fmaf(qv.z, ksr[d + 2], den);
            den = fmaf(qv.w, ksr[d + 3], den);
        }
        Out[((size_t)(b * LSEQ + l)) * DMOD + tid] = num / (den + 1e-6f);
    }
}

// ---------------- fused residual-add + LayerNorm (warp per row) --------------
__global__ void ln_add(const float* __restrict__ A, const float* __restrict__ Bt,
                       const float* __restrict__ gamma, const float* __restrict__ beta,
                       float* __restrict__ Out) {
    int row  = blockIdx.x * 8 + (threadIdx.x >> 5);
    int lane = threadIdx.x & 31;
    const float* a  = A  + (size_t)row * DMOD;
    const float* bb = Bt + (size_t)row * DMOD;

    int c0 = lane * 4, c1 = 128 + lane * 4;
    float4 x0 = *(const float4*)(a + c0);
    float4 x1 = *(const float4*)(a + c1);
    float4 y0 = *(const float4*)(bb + c0);
    float4 y1 = *(const float4*)(bb + c1);

    float v[8];
    v[0] = x0.x + y0.x; v[1] = x0.y + y0.y; v[2] = x0.z + y0.z; v[3] = x0.w + y0.w;
    v[4] = x1.x + y1.x; v[5] = x1.y + y1.y; v[6] = x1.z + y1.z; v[7] = x1.w + y1.w;

    float s = 0.f;
#pragma unroll
    for (int i = 0; i < 8; i++) s += v[i];
#pragma unroll
    for (int o = 16; o > 0; o >>= 1) s += __shfl_xor_sync(0xffffffffu, s, o);
    float mean = s * (1.0f / 256.0f);

    float q = 0.f;
#pragma unroll
    for (int i = 0; i < 8; i++) { float d = v[i] - mean; q += d * d; }
#pragma unroll
    for (int o = 16; o > 0; o >>= 1) q += __shfl_xor_sync(0xffffffffu, q, o);
    float inv = rsqrtf(q * (1.0f / 256.0f) + 1e-5f);

    float* op = Out + (size_t)row * DMOD;
    float o8[8];
#pragma unroll
    for (int i = 0; i < 4; i++)
        o8[i] = (v[i] - mean) * inv * gamma[c0 + i] + beta[c0 + i];
#pragma unroll
    for (int i = 0; i < 4; i++)
        o8[4 + i] = (v[4 + i] - mean) * inv * gamma[c1 + i] + beta[c1 + i];
    *(float4*)(op + c0) = *(float4*)(o8);
    *(float4*)(op + c1) = *(float4*)(o8 + 4);
}

// ---------------- output writeback: out[n][c][l] = X[n][l][c] (smem transpose)
__global__ void write_out(const float* __restrict__ X, float* __restrict__ out) {
    __shared__ float s[32][33];
    int n  = blockIdx.y;
    int ct = blockIdx.x >> 7;      // 0..7
    int lt = blockIdx.x & 127;     // 0..127
    int c0 = ct * 32, l0 = lt * 32;
    int tid = threadIdx.x;

    // read: lanes over c (coalesced in X)
#pragma unroll
    for (int p = 0; p < 4; p++) {
        int l = p * 8 + (tid >> 5);
        int c = tid & 31;
        s[l][c] = X[((size_t)n * LSEQ + l0 + l) * DMOD + c0 + c];
    }
    __syncthreads();

    // write: lanes over l (coalesced in out)
#pragma unroll
    for (int p = 0; p < 4; p++) {
        int c = p * 8 + (tid >> 5);
        int l = tid & 31;
        out[((size_t)n * DMOD + c0 + c) * LSEQ + l0 + l] = s[l][c];
    }
}

// ---------------- host orchestration -----------------------------------------
extern "C" void kernel_launch(void* const* d_in, const int* in_sizes, int n_in,
                              void* d_out, int out_size) {
    const float* ref = (const float*)d_in[0];
    const float* src = (const float*)d_in[1];
    const float* Wq  = (const float*)d_in[2];
    const float* bq  = (const float*)d_in[3];
    const float* Wk  = (const float*)d_in[4];
    const float* bk  = (const float*)d_in[5];
    const float* Wv  = (const float*)d_in[6];
    const float* bv  = (const float*)d_in[7];
    const float* Wo  = (const float*)d_in[8];
    const float* bo  = (const float*)d_in[9];
    const float* W1  = (const float*)d_in[10];
    const float* b1  = (const float*)d_in[11];
    const float* W2  = (const float*)d_in[12];
    const float* b2  = (const float*)d_in[13];
    const float* G1  = (const float*)d_in[14];
    const float* Be1 = (const float*)d_in[15];
    const float* G2  = (const float*)d_in[16];
    const float* Be2 = (const float*)d_in[17];

    float *x, *p2, *q, *k, *v, *h, *kv, *ks, *kvp, *ksp;
    cudaGetSymbolAddress((void**)&x,   g_x);
    cudaGetSymbolAddress((void**)&p2,  g_p2);
    cudaGetSymbolAddress((void**)&q,   g_q);
    cudaGetSymbolAddress((void**)&k,   g_k);
    cudaGetSymbolAddress((void**)&v,   g_v);
    cudaGetSymbolAddress((void**)&h,   g_h);
    cudaGetSymbolAddress((void**)&kv,  g_kv);
    cudaGetSymbolAddress((void**)&ks,  g_ks);
    cudaGetSymbolAddress((void**)&kvp, g_kvp);
    cudaGetSymbolAddress((void**)&ksp, g_ksp);

    {
        dim3 pb(8 * 128, 8);   // (ctile*ltile, img*n)
        posenc_kernel<<<pb, 256>>>(ref, src, x, p2);
    }

    dim3 grid256(DMOD / BN, MROWS / BM);   // (2, 256)
    dim3 grid512(DFF  / BN, MROWS / BM);   // (4, 256)

    for (int li = 0; li < 4; li++) {
        const float* s = (li % 2 == 0) ? x : p2;   // self / cross
        size_t wo  = (size_t)li * DMOD * DMOD;
        size_t bo_ = (size_t)li * DMOD;
        size_t w1o = (size_t)li * DMOD * DFF;
        size_t w2o = (size_t)li * DFF * DMOD;
        size_t b1o = (size_t)li * DFF;

        gemm_tf32<<<grid256, 256>>>(x, Wq + wo, bq + bo_, q, MROWS, DMOD, DMOD, 1);
        gemm_tf32<<<grid256, 256>>>(s, Wk + wo, bk + bo_, k, MROWS, DMOD, DMOD, 1);
        gemm_tf32<<<grid256, 256>>>(s, Wv + wo, bv + bo_, v, MROWS, DMOD, DMOD, 0);

        kv_partial<<<BATCH * NHEAD * KVCH, 256>>>(k, v, kvp, ksp);
        kv_finalize<<<BATCH * NHEAD, 256>>>(kvp, ksp, kv, ks);
        attn_apply<<<BATCH * 32, 256>>>(q, kv, ks, k);   // msg -> k buffer

        gemm_tf32<<<grid256, 256>>>(k, Wo + wo, bo + bo_, v, MROWS, DMOD, DMOD, 0);
        ln_add<<<MROWS / 8, 256>>>(x, v, G1 + bo_, Be1 + bo_, x);

        gemm_tf32<<<grid512, 256>>>(x, W1 + w1o, b1 + b1o, h, MROWS, DFF, DMOD, 2);
        gemm_tf32<<<grid256, 256>>>(h, W2 + w2o, b2 + bo_, q, MROWS, DMOD, DFF, 0);
        ln_add<<<MROWS / 8, 256>>>(x, q, G2 + bo_, Be2 + bo_, x);
    }

    {
        dim3 wb(8 * 128, 8);
        write_out<<<wb, 256>>>(x, (float*)d_out);
    }
}

// round 3
// speedup vs baseline: 1.1313x; 1.0008x over previous
#include <cuda_runtime.h>
#include <math.h>
#include <stdint.h>

// Problem constants
#define BATCH 8          // 2N after concat
#define LSEQ  4096       // H*W
#define DMOD  256
#define DFF   512
#define NHEAD 8
#define HDIM  32
#define MROWS (BATCH * LSEQ)   // 32768
#define KVCH  16               // L-chunks for kv partial reduction

// ---------------- scratch (static device globals; no allocation) -------------
__device__ float g_x  [MROWS * DMOD];   // p1 (current)
__device__ float g_p2 [MROWS * DMOD];   // p2 (fixed across layers)
__device__ float g_q  [MROWS * DMOD];
__device__ float g_k  [MROWS * DMOD];
__device__ float g_v  [MROWS * DMOD];
__device__ float g_h  [MROWS * DFF];
__device__ float g_kv [BATCH * NHEAD * HDIM * HDIM];
__device__ float g_ks [BATCH * NHEAD * HDIM];
__device__ float g_kvp[BATCH * NHEAD * KVCH * HDIM * HDIM];
__device__ float g_ksp[BATCH * NHEAD * KVCH * HDIM];

// ---------------- helpers -----------------------------------------------------
__device__ __forceinline__ uint32_t f2tf32(float x) {
    uint32_t y;
    asm("cvt.rna.tf32.f32 %0, %1;" : "=r"(y) : "f"(x));
    return y;
}

__device__ __forceinline__ void mma_tf32(float* acc, const uint32_t* a, const uint32_t* b) {
    asm volatile(
        "mma.sync.aligned.m16n8k8.row.col.f32.tf32.tf32.f32 "
        "{%0,%1,%2,%3}, {%4,%5,%6,%7}, {%8,%9}, {%0,%1,%2,%3};\n"
        : "+f"(acc[0]), "+f"(acc[1]), "+f"(acc[2]), "+f"(acc[3])
        : "r"(a[0]), "r"(a[1]), "r"(a[2]), "r"(a[3]), "r"(b[0]), "r"(b[1]));
}

// ---------------- pos encoding + concat (transpose through smem) --------------
// input: [img][n][c][l] ; outputs p1/p2: [b][l][c]
// grid: (img, n, ctile(8) * ltile(128)); block 256
__global__ void posenc_kernel(const float* __restrict__ ref,
                              const float* __restrict__ src,
                              float* __restrict__ p1, float* __restrict__ p2) {
    __shared__ float s[32][33];
    int img = blockIdx.y >> 2;
    int n   = blockIdx.y & 3;
    int ct  = blockIdx.x >> 7;        // 0..7
    int lt  = blockIdx.x & 127;       // 0..127
    int c0  = ct * 32, l0 = lt * 32;
    int tid = threadIdx.x;

    const float* inp = (img == 0) ? ref : src;

    // load: lanes over l (coalesced), rows over c
#pragma unroll
    for (int p = 0; p < 4; p++) {
        int c = p * 8 + (tid >> 5);
        int l = tid & 31;
        s[c][l] = inp[((size_t)n * DMOD + c0 + c) * LSEQ + l0 + l];
    }
    __syncthreads();

    // write: lanes over c (coalesced), rows over l; add pe computed per (c,l)
#pragma unroll
    for (int p = 0; p < 4; p++) {
        int l = p * 8 + (tid >> 5);
        int c = tid & 31;
        int cg = c0 + c, lg = l0 + l;
        int ii = cg >> 2, jj = cg & 3;
        float dv  = __expf(-(float)ii * (logf(10000.0f) / 64.0f));
        int   w   = lg & 63, hh = lg >> 6;
        float arg = (jj < 2 ? (float)w : (float)hh) * dv;
        float pe  = (jj & 1) ? cosf(arg) : sinf(arg);
        float val = s[c][l] + pe;
        size_t o1 = ((size_t)(img * 4 + n) * LSEQ + lg) * DMOD + cg;
        size_t o2 = ((size_t)((1 - img) * 4 + n) * LSEQ + lg) * DMOD + cg;
        p1[o1] = val;
        p2[o2] = val;
    }
}

// ---------------- TF32 tensor-core GEMM --------------------------------------
// C[M,N] = A[M,K] @ W[K,N] + bias, + activation (0 none, 1 elu+1, 2 relu)
// Block tile 128x128x32, 256 threads = 8 warps, warp tile 64x32.
// Shared memory holds fragment-prepacked tf32 tiles.
#define BM 128
#define BN 128
#define BK 32

__global__ __launch_bounds__(256)
void gemm_tf32(const float* __restrict__ A, const float* __restrict__ W,
               const float* __restrict__ bias, float* __restrict__ C,
               int M, int N, int K, int act) {
    // A frag layout: [kc(4)][mt(8)][t(32)][r(4)]  -> 4096 u32 = 16KB
    // B frag layout: [kc(4)][nt(16)][t(32)][r(2)] -> 4096 u32 = 16KB
    __shared__ uint32_t As[4096];
    __shared__ uint32_t Bs[4096];

    int bm = blockIdx.y * BM;
    int bn = blockIdx.x * BN;
    int tid  = threadIdx.x;
    int lane = tid & 31;
    int warp = tid >> 5;
    int wm = warp >> 2;          // 0..1 (m)
    int wn = warp & 3;           // 0..3 (n)
    int g  = lane >> 2;          // 0..7
    int t4 = lane & 3;           // 0..3

    float acc[4][4][4];
#pragma unroll
    for (int i = 0; i < 4; i++)
#pragma unroll
        for (int j = 0; j < 4; j++)
#pragma unroll
            for (int r = 0; r < 4; r++) acc[i][j][r] = 0.0f;

    for (int k0 = 0; k0 < K; k0 += BK) {
        // ---- load A tile 128x32 into fragment layout ----
#pragma unroll
        for (int it = 0; it < 4; it++) {
            int f = tid + it * 256;            // 0..1023 float4 slots
            int row = f >> 3;                  // 0..127
            int kbase = (f & 7) * 4;           // 0..28
            float4 v = *(const float4*)(A + (size_t)(bm + row) * K + k0 + kbase);
            float e[4] = {v.x, v.y, v.z, v.w};
            int mt = row >> 4;
            int rr = row & 15;
#pragma unroll
            for (int q = 0; q < 4; q++) {
                int k  = kbase + q;
                int kc = k >> 3, col = k & 7;
                int t  = ((rr & 7) << 2) | (col & 3);
                int r  = (rr >> 3) | ((col >> 2) << 1);
                As[((((kc << 3) + mt) << 5) + t) * 4 + r] = f2tf32(e[q]);
            }
        }
        // ---- load B tile 32x128 into fragment layout ----
#pragma unroll
        for (int it = 0; it < 4; it++) {
            int f = tid + it * 256;
            int krow = f >> 5;                 // 0..31
            int ncol = (f & 31) * 4;           // 0..124
            float4 v = *(const float4*)(W + (size_t)(k0 + krow) * N + bn + ncol);
            float e[4] = {v.x, v.y, v.z, v.w};
            int kc = krow >> 3, kr = krow & 7;
            int t4b = kr & 3, rb = kr >> 2;
#pragma unroll
            for (int q = 0; q < 4; q++) {
                int n  = ncol + q;
                int nt = n >> 3, gb = n & 7;
                int t  = (gb << 2) | t4b;
                Bs[((((kc << 4) + nt) << 5) + t) * 2 + rb] = f2tf32(e[q]);
            }
        }
        __syncthreads();

#pragma unroll
        for (int kc = 0; kc < 4; kc++) {
            uint32_t a[4][4], b[4][2];
#pragma unroll
            for (int i = 0; i < 4; i++) {
                int mt = wm * 4 + i;
                uint4 va = *(const uint4*)&As[((((kc << 3) + mt) << 5) + lane) * 4];
                a[i][0] = va.x; a[i][1] = va.y; a[i][2] = va.z; a[i][3] = va.w;
            }
#pragma unroll
            for (int j = 0; j < 4; j++) {
                int nt = wn * 4 + j;
                uint2 vb = *(const uint2*)&Bs[((((kc << 4) + nt) << 5) + lane) * 2];
                b[j][0] = vb.x; b[j][1] = vb.y;
            }
#pragma unroll
            for (int i = 0; i < 4; i++)
#pragma unroll
                for (int j = 0; j < 4; j++)
                    mma_tf32(acc[i][j], a[i], b[j]);
        }
        __syncthreads();
    }

    // ---- epilogue: bias + activation, float2 stores ----
#pragma unroll
    for (int j = 0; j < 4; j++) {
        int col = bn + wn * 32 + j * 8 + t4 * 2;
        float2 bv = *(const float2*)(bias + col);
#pragma unroll
        for (int i = 0; i < 4; i++) {
            int row0 = bm + wm * 64 + i * 16 + g;
#pragma unroll
            for (int half = 0; half < 2; half++) {
                int row = row0 + half * 8;
                float v0 = acc[i][j][half * 2 + 0] + bv.x;
                float v1 = acc[i][j][half * 2 + 1] + bv.y;
                if (act == 1) {
                    v0 = (v0 > 0.0f) ? (v0 + 1.0f) : __expf(v0);
                    v1 = (v1 > 0.0f) ? (v1 + 1.0f) : __expf(v1);
                } else if (act == 2) {
                    v0 = fmaxf(v0, 0.0f);
                    v1 = fmaxf(v1, 0.0f);
                }
                float2 out = make_float2(v0, v1);
                *(float2*)(C + (size_t)row * N + col) = out;
            }
        }
    }
}

// ---------------- KV partial reduction (stage 1) ------------------------------
// grid: 64*KVCH blocks; each computes partial KV over 256 rows of L.
__global__ void kv_partial(const float* __restrict__ Kin, const float* __restrict__ Vin,
                           float* __restrict__ KVp, float* __restrict__ Ksp) {
    int blk = blockIdx.x;
    int bh = blk >> 4;            // 0..63
    int ch = blk & (KVCH - 1);    // 0..15
    int b  = bh >> 3;
    int h  = bh & 7;
    int tid = threadIdx.x;        // 256

    __shared__ float Ks[32][36];
    __shared__ float Vs[32][32];

    int m  = tid >> 3;            // 0..31
    int d0 = (tid & 7) * 4;       // 0..28

    float acc[4] = {0.f, 0.f, 0.f, 0.f};
    float ks[4]  = {0.f, 0.f, 0.f, 0.f};

    int lr = tid >> 3;
    int lc = (tid & 7) * 4;

    int lbeg = ch * (LSEQ / KVCH);
    int lend = lbeg + (LSEQ / KVCH);
    for (int l0 = lbeg; l0 < lend; l0 += 32) {
        size_t base = ((size_t)(b * LSEQ + l0 + lr)) * DMOD + h * HDIM + lc;
        float4 kv4 = *(const float4*)(Kin + base);
        float4 vv4 = *(const float4*)(Vin + base);
        Ks[lr][lc + 0] = kv4.x; Ks[lr][lc + 1] = kv4.y;
        Ks[lr][lc + 2] = kv4.z; Ks[lr][lc + 3] = kv4.w;
        *(float4*)&Vs[lr][lc] = vv4;
        __syncthreads();

#pragma unroll 8
        for (int r = 0; r < 32; r++) {
            float vm = Vs[r][m];
#pragma unroll
            for (int j = 0; j < 4; j++)
                acc[j] = fmaf(vm, Ks[r][d0 + j], acc[j]);
            if (m == 0) {
#pragma unroll
                for (int j = 0; j < 4; j++) ks[j] += Ks[r][d0 + j];
            }
        }
        __syncthreads();
    }

    size_t obase = ((size_t)blk * HDIM + m) * HDIM + d0;
#pragma unroll
    for (int j = 0; j < 4; j++) KVp[obase + j] = acc[j];
    if (m == 0) {
#pragma unroll
        for (int j = 0; j < 4; j++) Ksp[blk * HDIM + d0 + j] = ks[j];
    }
}

// ---------------- KV finalize (stage 2) ---------------------------------------
__global__ void kv_finalize(const float* __restrict__ KVp, const float* __restrict__ Ksp,
                            float* __restrict__ KV, float* __restrict__ Ksum) {
    int bh = blockIdx.x;
    int tid = threadIdx.x;
#pragma unroll
    for (int o = 0; o < 4; o++) {
        int idx = tid + o * 256;          // 0..1023 (m*32+d)
        float s = 0.f;
#pragma unroll
        for (int c = 0; c < KVCH; c++)
            s += KVp[((size_t)(bh * KVCH + c)) * (HDIM * HDIM) + idx];
        KV[(size_t)bh * (HDIM * HDIM) + idx] = s;
    }
    if (tid < HDIM) {
        float s = 0.f;
#pragma unroll
        for (int c = 0; c < KVCH; c++)
            s += Ksp[(bh * KVCH + c) * HDIM + tid];
        Ksum[bh * HDIM + tid] = s;
    }
}

// ---------------- attention apply ---------------------------------------------
__global__ void attn_apply(const float* __restrict__ Q, const float* __restrict__ KV,
                           const float* __restrict__ Ksum, float* __restrict__ Out) {
    int blk = blockIdx.x;          // b*32 + tile
    int b   = blk >> 5;
    int lt  = (blk & 31) * 128;
    int tid = threadIdx.x;         // 256 -> one output channel

    __shared__ float KVs[NHEAD * HDIM * 33];
    __shared__ float Ksums[NHEAD * HDIM];

    for (int i = tid; i < NHEAD * HDIM * HDIM; i += 256) {
        int h = i >> 10, m = (i >> 5) & 31, d = i & 31;
        KVs[(h * HDIM + m) * 33 + d] = KV[((size_t)(b * NHEAD + h) * HDIM + m) * HDIM + d];
    }
    for (int i = tid; i < NHEAD * HDIM; i += 256)
        Ksums[i] = Ksum[b * NHEAD * HDIM + i];
    __syncthreads();

    int h = tid >> 5, m = tid & 31;
    const float* kvrow = &KVs[(h * HDIM + m) * 33];
    const float* ksr   = &Ksums[h * HDIM];

    for (int r = 0; r < 128; r++) {
        int l = lt + r;
        const float* q = Q + ((size_t)(b * LSEQ + l)) * DMOD + h * HDIM;
        float num = 0.f, den = 0.f;
#pragma unroll
        for (int d = 0; d < HDIM; d += 4) {
            float4 qv = *(const float4*)(q + d);
            num = fmaf(qv.x, kvrow[d],     num);
            num = fmaf(qv.y, kvrow[d + 1], num);
            num = fmaf(qv.z, kvrow[d + 2], num);
            num = fmaf(qv.w, kvrow[d + 3], num);
            den = fmaf(qv.x, ksr[d],     den);
            den = fmaf(qv.y, ksr[d + 1], den);
            den = fmaf(qv.z, ksr[d + 2], den);
            den = fmaf(qv.w, ksr[d + 3], den);
        }
        Out[((size_t)(b * LSEQ + l)) * DMOD + tid] = num / (den + 1e-6f);
    }
}

// ---------------- fused residual-add + LayerNorm (warp per row) --------------
__global__ void ln_add(const float* __restrict__ A, const float* __restrict__ Bt,
                       const float* __restrict__ gamma, const float* __restrict__ beta,
                       float* __restrict__ Out) {
    int row  = blockIdx.x * 8 + (threadIdx.x >> 5);
    int lane = threadIdx.x & 31;
    const float* a  = A  + (size_t)row * DMOD;
    const float* bb = Bt + (size_t)row * DMOD;

    int c0 = lane * 4, c1 = 128 + lane * 4;
    float4 x0 = *(const float4*)(a + c0);
    float4 x1 = *(const float4*)(a + c1);
    float4 y0 = *(const float4*)(bb + c0);
    float4 y1 = *(const float4*)(bb + c1);

    float v[8];
    v[0] = x0.x + y0.x; v[1] = x0.y + y0.y; v[2] = x0.z + y0.z; v[3] = x0.w + y0.w;
    v[4] = x1.x + y1.x; v[5] = x1.y + y1.y; v[6] = x1.z + y1.z; v[7] = x1.w + y1.w;

    float s = 0.f;
#pragma unroll
    for (int i = 0; i < 8; i++) s += v[i];
#pragma unroll
    for (int o = 16; o > 0; o >>= 1) s += __shfl_xor_sync(0xffffffffu, s, o);
    float mean = s * (1.0f / 256.0f);

    float q = 0.f;
#pragma unroll
    for (int i = 0; i < 8; i++) { float d = v[i] - mean; q += d * d; }
#pragma unroll
    for (int o = 16; o > 0; o >>= 1) q += __shfl_xor_sync(0xffffffffu, q, o);
    float inv = rsqrtf(q * (1.0f / 256.0f) + 1e-5f);

    float* op = Out + (size_t)row * DMOD;
    float o8[8];
#pragma unroll
    for (int i = 0; i < 4; i++)
        o8[i] = (v[i] - mean) * inv * gamma[c0 + i] + beta[c0 + i];
#pragma unroll
    for (int i = 0; i < 4; i++)
        o8[4 + i] = (v[4 + i] - mean) * inv * gamma[c1 + i] + beta[c1 + i];
    *(float4*)(op + c0) = *(float4*)(o8);
    *(float4*)(op + c1) = *(float4*)(o8 + 4);
}

// ---------------- output writeback: out[n][c][l] = X[n][l][c] (smem transpose)
__global__ void write_out(const float* __restrict__ X, float* __restrict__ out) {
    __shared__ float s[32][33];
    int n  = blockIdx.y;
    int ct = blockIdx.x >> 7;      // 0..7
    int lt = blockIdx.x & 127;     // 0..127
    int c0 = ct * 32, l0 = lt * 32;
    int tid = threadIdx.x;

    // read: lanes over c (coalesced in X)
#pragma unroll
    for (int p = 0; p < 4; p++) {
        int l = p * 8 + (tid >> 5);
        int c = tid & 31;
        s[l][c] = X[((size_t)n * LSEQ + l0 + l) * DMOD + c0 + c];
    }
    __syncthreads();

    // write: lanes over l (coalesced in out)
#pragma unroll
    for (int p = 0; p < 4; p++) {
        int c = p * 8 + (tid >> 5);
        int l = tid & 31;
        out[((size_t)n * DMOD + c0 + c) * LSEQ + l0 + l] = s[l][c];
    }
}

// ---------------- host orchestration -----------------------------------------
extern "C" void kernel_launch(void* const* d_in, const int* in_sizes, int n_in,
                              void* d_out, int out_size) {
    const float* ref = (const float*)d_in[0];
    const float* src = (const float*)d_in[1];
    const float* Wq  = (const float*)d_in[2];
    const float* bq  = (const float*)d_in[3];
    const float* Wk  = (const float*)d_in[4];
    const float* bk  = (const float*)d_in[5];
    const float* Wv  = (const float*)d_in[6];
    const float* bv  = (const float*)d_in[7];
    const float* Wo  = (const float*)d_in[8];
    const float* bo  = (const float*)d_in[9];
    const float* W1  = (const float*)d_in[10];
    const float* b1  = (const float*)d_in[11];
    const float* W2  = (const float*)d_in[12];
    const float* b2  = (const float*)d_in[13];
    const float* G1  = (const float*)d_in[14];
    const float* Be1 = (const float*)d_in[15];
    const float* G2  = (const float*)d_in[16];
    const float* Be2 = (const float*)d_in[17];

    float *x, *p2, *q, *k, *v, *h, *kv, *ks, *kvp, *ksp;
    cudaGetSymbolAddress((void**)&x,   g_x);
    cudaGetSymbolAddress((void**)&p2,  g_p2);
    cudaGetSymbolAddress((void**)&q,   g_q);
    cudaGetSymbolAddress((void**)&k,   g_k);
    cudaGetSymbolAddress((void**)&v,   g_v);
    cudaGetSymbolAddress((void**)&h,   g_h);
    cudaGetSymbolAddress((void**)&kv,  g_kv);
    cudaGetSymbolAddress((void**)&ks,  g_ks);
    cudaGetSymbolAddress((void**)&kvp, g_kvp);
    cudaGetSymbolAddress((void**)&ksp, g_ksp);

    {
        dim3 pb(8 * 128, 8);   // (ctile*ltile, img*n)
        posenc_kernel<<<pb, 256>>>(ref, src, x, p2);
    }

    dim3 grid256(DMOD / BN, MROWS / BM);   // (2, 256)
    dim3 grid512(DFF  / BN, MROWS / BM);   // (4, 256)

    for (int li = 0; li < 4; li++) {
        const float* s = (li % 2 == 0) ? x : p2;   // self / cross
        size_t wo  = (size_t)li * DMOD * DMOD;
        size_t bo_ = (size_t)li * DMOD;
        size_t w1o = (size_t)li * DMOD * DFF;
        size_t w2o = (size_t)li * DFF * DMOD;
        size_t b1o = (size_t)li * DFF;

        gemm_tf32<<<grid256, 256>>>(x, Wq + wo, bq + bo_, q, MROWS, DMOD, DMOD, 1);
        gemm_tf32<<<grid256, 256>>>(s, Wk + wo, bk + bo_, k, MROWS, DMOD, DMOD, 1);
        gemm_tf32<<<grid256, 256>>>(s, Wv + wo, bv + bo_, v, MROWS, DMOD, DMOD, 0);

        kv_partial<<<BATCH * NHEAD * KVCH, 256>>>(k, v, kvp, ksp);
        kv_finalize<<<BATCH * NHEAD, 256>>>(kvp, ksp, kv, ks);
        attn_apply<<<BATCH * 32, 256>>>(q, kv, ks, k);   // msg -> k buffer

        gemm_tf32<<<grid256, 256>>>(k, Wo + wo, bo + bo_, v, MROWS, DMOD, DMOD, 0);
        ln_add<<<MROWS / 8, 256>>>(x, v, G1 + bo_, Be1 + bo_, x);

        gemm_tf32<<<grid512, 256>>>(x, W1 + w1o, b1 + b1o, h, MROWS, DFF, DMOD, 2);
        gemm_tf32<<<grid256, 256>>>(h, W2 + w2o, b2 + bo_, q, MROWS, DMOD, DFF, 0);
        ln_add<<<MROWS / 8, 256>>>(x, q, G2 + bo_, Be2 + bo_, x);
    }

    {
        dim3 wb(8 * 128, 8);
        write_out<<<wb, 256>>>(x, (float*)d_out);
    }
}

// round 5
// speedup vs baseline: 2.0504x; 1.8124x over previous
#include <cuda_runtime.h>
#include <cuda_fp16.h>
#include <math.h>
#include <stdint.h>

#define BATCH 8
#define LSEQ  4096
#define DMOD  256
#define DFF   512
#define NHEAD 8
#define HDIM  32
#define MROWS (BATCH * LSEQ)   // 32768
#define KVCH  16

// GEMM: 128x128 CTA tile, K-tile of 64 halves (128B rows), 2-stage cp.async pipeline
#define STG   65536            // Ah|Al|Bh|Bl each 16KB
#define GSMEM (2 * STG)

// ---------------- scratch ------------------------------------------------------
__device__ float g_x [MROWS * DMOD];
__device__ float g_q [MROWS * DMOD];
__device__ float g_k [MROWS * DMOD];
__device__ float g_v [MROWS * DMOD];
__device__ float g_kv [BATCH * NHEAD * HDIM * HDIM];
__device__ float g_ks [BATCH * NHEAD * HDIM];
__device__ float g_kvp[BATCH * NHEAD * KVCH * HDIM * HDIM];
__device__ float g_ksp[BATCH * NHEAD * KVCH * HDIM];

__device__ __half g_xh [MROWS * DMOD];
__device__ __half g_xl [MROWS * DMOD];
__device__ __half g_p2h[MROWS * DMOD];
__device__ __half g_p2l[MROWS * DMOD];
__device__ __half g_mh [MROWS * DMOD];
__device__ __half g_ml [MROWS * DMOD];
__device__ __half g_hh [MROWS * DFF];
__device__ __half g_hl [MROWS * DFF];
// transposed weights per layer: q@0 k@65536 v@131072 o@196608 w1t@262144 w2t@393216
#define WLAYER 524288
__device__ __half g_wth[4 * WLAYER];
__device__ __half g_wtl[4 * WLAYER];

// ---------------- helpers -------------------------------------------------------
__device__ __forceinline__ uint32_t smem_u32(const void* p) {
    uint32_t a;
    asm("{ .reg .u64 t; cvta.to.shared.u64 t, %1; cvt.u32.u64 %0, t; }" : "=r"(a) : "l"(p));
    return a;
}
__device__ __forceinline__ uint32_t swz128(uint32_t off) { return off ^ ((off >> 3) & 0x70); }

__device__ __forceinline__ void cpa16(uint32_t dst, const void* src) {
    asm volatile("cp.async.cg.shared.global [%0], [%1], 16;" :: "r"(dst), "l"(src));
}
#define CPA_COMMIT() asm volatile("cp.async.commit_group;" ::: "memory")

__device__ __forceinline__ void ldsm4(uint32_t* r, uint32_t a) {
    asm volatile("ldmatrix.sync.aligned.m8n8.x4.shared.b16 {%0,%1,%2,%3}, [%4];"
                 : "=r"(r[0]), "=r"(r[1]), "=r"(r[2]), "=r"(r[3]) : "r"(a));
}
__device__ __forceinline__ void mma16816(float* c, const uint32_t* a, uint32_t b0, uint32_t b1) {
    asm volatile(
        "mma.sync.aligned.m16n8k16.row.col.f32.f16.f16.f32 "
        "{%0,%1,%2,%3},{%4,%5,%6,%7},{%8,%9},{%0,%1,%2,%3};"
        : "+f"(c[0]), "+f"(c[1]), "+f"(c[2]), "+f"(c[3])
        : "r"(a[0]), "r"(a[1]), "r"(a[2]), "r"(a[3]), "r"(b0), "r"(b1));
}

__device__ __forceinline__ void split2h(float x, __half& h, __half& l) {
    h = __float2half_rn(x);
    l = __float2half_rn(x - __half2float(h));
}

// ---------------- pos encoding + concat ------------------------------------------
__global__ void posenc_kernel(const float* __restrict__ ref, const float* __restrict__ src,
                              float* __restrict__ p1,
                              __half* __restrict__ p1h, __half* __restrict__ p1l,
                              __half* __restrict__ p2h, __half* __restrict__ p2l) {
    __shared__ float s[32][33];
    int img = blockIdx.y >> 2;
    int n   = blockIdx.y & 3;
    int ct  = blockIdx.x >> 7;
    int lt  = blockIdx.x & 127;
    int c0  = ct * 32, l0 = lt * 32;
    int tid = threadIdx.x;

    const float* inp = (img == 0) ? ref : src;
#pragma unroll
    for (int p = 0; p < 4; p++) {
        int c = p * 8 + (tid >> 5);
        int l = tid & 31;
        s[c][l] = inp[((size_t)n * DMOD + c0 + c) * LSEQ + l0 + l];
    }
    __syncthreads();
#pragma unroll
    for (int p = 0; p < 4; p++) {
        int l = p * 8 + (tid >> 5);
        int c = tid & 31;
        int cg = c0 + c, lg = l0 + l;
        int ii = cg >> 2, jj = cg & 3;
        float dv  = __expf(-(float)ii * (logf(10000.0f) / 64.0f));
        int   w   = lg & 63, hh = lg >> 6;
        float arg = (jj < 2 ? (float)w : (float)hh) * dv;
        float pe  = (jj & 1) ? cosf(arg) : sinf(arg);
        float val = s[c][l] + pe;
        size_t o1 = ((size_t)(img * 4 + n) * LSEQ + lg) * DMOD + cg;
        size_t o2 = ((size_t)((1 - img) * 4 + n) * LSEQ + lg) * DMOD + cg;
        __half h, lo;
        split2h(val, h, lo);
        p1[o1] = val; p1h[o1] = h; p1l[o1] = lo;
        p2h[o2] = h;  p2l[o2] = lo;
    }
}

// ---------------- weight transpose + split: W[K,N] -> T[N,K] hi/lo ---------------
__global__ void wconv(const float* __restrict__ W, __half* __restrict__ Th,
                      __half* __restrict__ Tl, int K, int N) {
    __shared__ float s[32][33];
    int n0 = blockIdx.x * 32, k0 = blockIdx.y * 32;
    int tid = threadIdx.x;
#pragma unroll
    for (int p = 0; p < 4; p++) {
        int kk = p * 8 + (tid >> 5), nn = tid & 31;
        s[kk][nn] = W[(size_t)(k0 + kk) * N + n0 + nn];
    }
    __syncthreads();
#pragma unroll
    for (int p = 0; p < 4; p++) {
        int nn = p * 8 + (tid >> 5), kk = tid & 31;
        float v = s[kk][nn];
        __half h, l;
        split2h(v, h, l);
        Th[(size_t)(n0 + nn) * K + k0 + kk] = h;
        Tl[(size_t)(n0 + nn) * K + k0 + kk] = l;
    }
}

// ---------------- fp16-pair GEMM (ldmatrix + mma.m16n8k16 + cp.async) -------------
// C[M,N] = (Ah+Al)[M,K] @ (Bh+Bl)[N,K]^T + bias
// mode: 0 fp32 out; 1 fp32 + elu+1; 2 half-pair + relu
__device__ __forceinline__ void load_stage(const __half* Ah, const __half* Al,
                                           const __half* Bh, const __half* Bl,
                                           int bm, int bn, int K, int k0,
                                           uint32_t sb, int tid) {
#pragma unroll
    for (int it = 0; it < 4; it++) {
        int c = tid + it * 256;          // 0..1023
        int r = c >> 3, seg = c & 7;
        uint32_t d = swz128((uint32_t)(r * 128 + seg * 16));
        size_t ga = (size_t)(bm + r) * K + k0 + seg * 8;
        size_t gb = (size_t)(bn + r) * K + k0 + seg * 8;
        cpa16(sb + d,         Ah + ga);
        cpa16(sb + 16384 + d, Al + ga);
        cpa16(sb + 32768 + d, Bh + gb);
        cpa16(sb + 49152 + d, Bl + gb);
    }
    CPA_COMMIT();
}

__global__ __launch_bounds__(256, 1)
void gemm_hp(const __half* __restrict__ Ah, const __half* __restrict__ Al,
             const __half* __restrict__ Bh, const __half* __restrict__ Bl,
             const float* __restrict__ bias,
             float* __restrict__ Cf, __half* __restrict__ Ch, __half* __restrict__ Cl,
             int M, int N, int K, int mode) {
    extern __shared__ char smem[];
    uint32_t sb = smem_u32(smem);
    int tid  = threadIdx.x;
    int lane = tid & 31;
    int warp = tid >> 5;
    int wm = warp >> 2;      // 0..1
    int wn = warp & 3;       // 0..3
    int bm = blockIdx.y * 128, bn = blockIdx.x * 128;

    float acc[4][4][4];
#pragma unroll
    for (int i = 0; i < 4; i++)
#pragma unroll
        for (int j = 0; j < 4; j++)
#pragma unroll
            for (int r = 0; r < 4; r++) acc[i][j][r] = 0.0f;

    const int KT = K >> 6;
    load_stage(Ah, Al, Bh, Bl, bm, bn, K, 0, sb, tid);

    int lrow = (lane & 7) + ((lane >> 3) & 1) * 8;   // 0..15
    int kseg = (lane >> 4) * 16;                     // 0 or 16 bytes

    for (int kt = 0; kt < KT; kt++) {
        if (kt + 1 < KT) {
            load_stage(Ah, Al, Bh, Bl, bm, bn, K, (kt + 1) << 6,
                       sb + ((kt + 1) & 1) * STG, tid);
            asm volatile("cp.async.wait_group 1;" ::: "memory");
        } else {
            asm volatile("cp.async.wait_group 0;" ::: "memory");
        }
        __syncthreads();

        uint32_t offA  = sb + (kt & 1) * STG;
        uint32_t offAl = offA + 16384;
        uint32_t offB  = offA + 32768;
        uint32_t offBl = offA + 49152;

#pragma unroll
        for (int kk = 0; kk < 4; kk++) {
            int kb = kk * 32 + kseg;
            uint32_t ah[4][4], al[4][4], bh[2][4], bl[2][4];
#pragma unroll
            for (int mt = 0; mt < 4; mt++) {
                uint32_t off = swz128((uint32_t)((wm * 64 + mt * 16 + lrow) * 128 + kb));
                ldsm4(ah[mt], offA  + off);
                ldsm4(al[mt], offAl + off);
            }
#pragma unroll
            for (int j = 0; j < 2; j++) {
                uint32_t off = swz128((uint32_t)((wn * 32 + j * 16 + lrow) * 128 + kb));
                ldsm4(bh[j], offB  + off);
                ldsm4(bl[j], offBl + off);
            }
#pragma unroll
            for (int mt = 0; mt < 4; mt++)
#pragma unroll
                for (int n8 = 0; n8 < 4; n8++) {
                    int j = n8 >> 1, s = n8 & 1;
                    mma16816(acc[mt][n8], ah[mt], bh[j][s], bh[j][2 + s]);
                    mma16816(acc[mt][n8], ah[mt], bl[j][s], bl[j][2 + s]);
                    mma16816(acc[mt][n8], al[mt], bh[j][s], bh[j][2 + s]);
                }
        }
        __syncthreads();
    }

    // ---- epilogue ----
    int gid = lane >> 2, tig = lane & 3;
#pragma unroll
    for (int n8 = 0; n8 < 4; n8++) {
        int col = bn + wn * 32 + n8 * 8 + tig * 2;
        float2 bv = *(const float2*)(bias + col);
#pragma unroll
        for (int mt = 0; mt < 4; mt++) {
            int row0 = bm + wm * 64 + mt * 16 + gid;
#pragma unroll
            for (int half = 0; half < 2; half++) {
                int row = row0 + half * 8;
                float v0 = acc[mt][n8][half * 2 + 0] + bv.x;
                float v1 = acc[mt][n8][half * 2 + 1] + bv.y;
                if (mode == 1) {
                    v0 = (v0 > 0.f) ? v0 + 1.f : __expf(v0);
                    v1 = (v1 > 0.f) ? v1 + 1.f : __expf(v1);
                } else if (mode == 2) {
                    v0 = fmaxf(v0, 0.f);
                    v1 = fmaxf(v1, 0.f);
                }
                if (mode == 2) {
                    __half h0, l0, h1, l1;
                    split2h(v0, h0, l0);
                    split2h(v1, h1, l1);
                    *(__half2*)(Ch + (size_t)row * N + col) = __halves2half2(h0, h1);
                    *(__half2*)(Cl + (size_t)row * N + col) = __halves2half2(l0, l1);
                } else {
                    *(float2*)(Cf + (size_t)row * N + col) = make_float2(v0, v1);
                }
            }
        }
    }
}

// ---------------- KV partial reduction --------------------------------------------
__global__ void kv_partial(const float* __restrict__ Kin, const float* __restrict__ Vin,
                           float* __restrict__ KVp, float* __restrict__ Ksp) {
    int blk = blockIdx.x;
    int bh = blk >> 4;
    int ch = blk & (KVCH - 1);
    int b  = bh >> 3;
    int h  = bh & 7;
    int tid = threadIdx.x;

    __shared__ float Ks[32][36];
    __shared__ float Vs[32][32];

    int m  = tid >> 3;
    int d0 = (tid & 7) * 4;
    float acc[4] = {0.f, 0.f, 0.f, 0.f};
    float ks[4]  = {0.f, 0.f, 0.f, 0.f};
    int lr = tid >> 3, lc = (tid & 7) * 4;

    int lbeg = ch * (LSEQ / KVCH);
    int lend = lbeg + (LSEQ / KVCH);
    for (int l0 = lbeg; l0 < lend; l0 += 32) {
        size_t base = ((size_t)(b * LSEQ + l0 + lr)) * DMOD + h * HDIM + lc;
        float4 kv4 = *(const float4*)(Kin + base);
        float4 vv4 = *(const float4*)(Vin + base);
        Ks[lr][lc + 0] = kv4.x; Ks[lr][lc + 1] = kv4.y;
        Ks[lr][lc + 2] = kv4.z; Ks[lr][lc + 3] = kv4.w;
        *(float4*)&Vs[lr][lc] = vv4;
        __syncthreads();
#pragma unroll 8
        for (int r = 0; r < 32; r++) {
            float vm = Vs[r][m];
#pragma unroll
            for (int j = 0; j < 4; j++) acc[j] = fmaf(vm, Ks[r][d0 + j], acc[j]);
            if (m == 0) {
#pragma unroll
                for (int j = 0; j < 4; j++) ks[j] += Ks[r][d0 + j];
            }
        }
        __syncthreads();
    }
    size_t obase = ((size_t)blk * HDIM + m) * HDIM + d0;
#pragma unroll
    for (int j = 0; j < 4; j++) KVp[obase + j] = acc[j];
    if (m == 0) {
#pragma unroll
        for (int j = 0; j < 4; j++) Ksp[blk * HDIM + d0 + j] = ks[j];
    }
}

__global__ void kv_finalize(const float* __restrict__ KVp, const float* __restrict__ Ksp,
                            float* __restrict__ KV, float* __restrict__ Ksum) {
    int bh = blockIdx.x;
    int tid = threadIdx.x;
#pragma unroll
    for (int o = 0; o < 4; o++) {
        int idx = tid + o * 256;
        float s = 0.f;
#pragma unroll
        for (int c = 0; c < KVCH; c++)
            s += KVp[((size_t)(bh * KVCH + c)) * (HDIM * HDIM) + idx];
        KV[(size_t)bh * (HDIM * HDIM) + idx] = s;
    }
    if (tid < HDIM) {
        float s = 0.f;
#pragma unroll
        for (int c = 0; c < KVCH; c++)
            s += Ksp[(bh * KVCH + c) * HDIM + tid];
        Ksum[bh * HDIM + tid] = s;
    }
}

// ---------------- attention apply (emits half hi/lo message) ----------------------
__global__ void attn_apply(const float* __restrict__ Q, const float* __restrict__ KV,
                           const float* __restrict__ Ksum,
                           __half* __restrict__ Mh, __half* __restrict__ Ml) {
    int blk = blockIdx.x;
    int b   = blk >> 5;
    int lt  = (blk & 31) * 128;
    int tid = threadIdx.x;

    __shared__ float KVs[NHEAD * HDIM * 33];
    __shared__ float Ksums[NHEAD * HDIM];

    for (int i = tid; i < NHEAD * HDIM * HDIM; i += 256) {
        int h = i >> 10, m = (i >> 5) & 31, d = i & 31;
        KVs[(h * HDIM + m) * 33 + d] = KV[((size_t)(b * NHEAD + h) * HDIM + m) * HDIM + d];
    }
    for (int i = tid; i < NHEAD * HDIM; i += 256)
        Ksums[i] = Ksum[b * NHEAD * HDIM + i];
    __syncthreads();

    int h = tid >> 5, m = tid & 31;
    const float* kvrow = &KVs[(h * HDIM + m) * 33];
    const float* ksr   = &Ksums[h * HDIM];

    for (int r = 0; r < 128; r++) {
        int l = lt + r;
        const float* q = Q + ((size_t)(b * LSEQ + l)) * DMOD + h * HDIM;
        float num = 0.f, den = 0.f;
#pragma unroll
        for (int d = 0; d < HDIM; d += 4) {
            float4 qv = *(const float4*)(q + d);
            num = fmaf(qv.x, kvrow[d],     num);
            num = fmaf(qv.y, kvrow[d + 1], num);
            num = fmaf(qv.z, kvrow[d + 2], num);
            num = fmaf(qv.w, kvrow[d + 3], num);
            den = fmaf(qv.x, ksr[d],     den);
            den = fmaf(qv.y, ksr[d + 1], den);
            den = fmaf(qv.z, ksr[d + 2], den);
            den = fmaf(qv.w, ksr[d + 3], den);
        }
        float o = num / (den + 1e-6f);
        __half hh, ll;
        split2h(o, hh, ll);
        size_t oi = ((size_t)(b * LSEQ + l)) * DMOD + tid;
        Mh[oi] = hh; Ml[oi] = ll;
    }
}

// ---------------- fused residual + LayerNorm (fp32 + half pair out) ---------------
__global__ void ln_add(const float* __restrict__ A, const float* __restrict__ Bt,
                       const float* __restrict__ gamma, const float* __restrict__ beta,
                       float* __restrict__ Out,
                       __half* __restrict__ Oh, __half* __restrict__ Ol) {
    int row  = blockIdx.x * 8 + (threadIdx.x >> 5);
    int lane = threadIdx.x & 31;
    const float* a  = A  + (size_t)row * DMOD;
    const float* bb = Bt + (size_t)row * DMOD;

    int c0 = lane * 4, c1 = 128 + lane * 4;
    float4 x0 = *(const float4*)(a + c0);
    float4 x1 = *(const float4*)(a + c1);
    float4 y0 = *(const float4*)(bb + c0);
    float4 y1 = *(const float4*)(bb + c1);

    float v[8];
    v[0] = x0.x + y0.x; v[1] = x0.y + y0.y; v[2] = x0.z + y0.z; v[3] = x0.w + y0.w;
    v[4] = x1.x + y1.x; v[5] = x1.y + y1.y; v[6] = x1.z + y1.z; v[7] = x1.w + y1.w;

    float s = 0.f;
#pragma unroll
    for (int i = 0; i < 8; i++) s += v[i];
#pragma unroll
    for (int o = 16; o > 0; o >>= 1) s += __shfl_xor_sync(0xffffffffu, s, o);
    float mean = s * (1.0f / 256.0f);

    float qv = 0.f;
#pragma unroll
    for (int i = 0; i < 8; i++) { float d = v[i] - mean; qv += d * d; }
#pragma unroll
    for (int o = 16; o > 0; o >>= 1) qv += __shfl_xor_sync(0xffffffffu, qv, o);
    float inv = rsqrtf(qv * (1.0f / 256.0f) + 1e-5f);

    float o8[8];
#pragma unroll
    for (int i = 0; i < 4; i++)
        o8[i] = (v[i] - mean) * inv * gamma[c0 + i] + beta[c0 + i];
#pragma unroll
    for (int i = 0; i < 4; i++)
        o8[4 + i] = (v[4 + i] - mean) * inv * gamma[c1 + i] + beta[c1 + i];

    float* op = Out + (size_t)row * DMOD;
    *(float4*)(op + c0) = *(float4*)(o8);
    *(float4*)(op + c1) = *(float4*)(o8 + 4);

    union { __half b[4]; uint2 u; } h0, l0, h1, l1;
#pragma unroll
    for (int i = 0; i < 4; i++) split2h(o8[i],     h0.b[i], l0.b[i]);
#pragma unroll
    for (int i = 0; i < 4; i++) split2h(o8[4 + i], h1.b[i], l1.b[i]);
    *(uint2*)(Oh + (size_t)row * DMOD + c0) = h0.u;
    *(uint2*)(Ol + (size_t)row * DMOD + c0) = l0.u;
    *(uint2*)(Oh + (size_t)row * DMOD + c1) = h1.u;
    *(uint2*)(Ol + (size_t)row * DMOD + c1) = l1.u;
}

// ---------------- output writeback -------------------------------------------------
__global__ void write_out(const float* __restrict__ X, float* __restrict__ out) {
    __shared__ float s[32][33];
    int n  = blockIdx.y;
    int ct = blockIdx.x >> 7;
    int lt = blockIdx.x & 127;
    int c0 = ct * 32, l0 = lt * 32;
    int tid = threadIdx.x;
#pragma unroll
    for (int p = 0; p < 4; p++) {
        int l = p * 8 + (tid >> 5);
        int c = tid & 31;
        s[l][c] = X[((size_t)n * LSEQ + l0 + l) * DMOD + c0 + c];
    }
    __syncthreads();
#pragma unroll
    for (int p = 0; p < 4; p++) {
        int c = p * 8 + (tid >> 5);
        int l = tid & 31;
        out[((size_t)n * DMOD + c0 + c) * LSEQ + l0 + l] = s[l][c];
    }
}

// ---------------- host orchestration -----------------------------------------------
extern "C" void kernel_launch(void* const* d_in, const int* in_sizes, int n_in,
                              void* d_out, int out_size) {
    const float* ref = (const float*)d_in[0];
    const float* src = (const float*)d_in[1];
    const float* Wq  = (const float*)d_in[2];
    const float* bq  = (const float*)d_in[3];
    const float* Wk  = (const float*)d_in[4];
    const float* bk  = (const float*)d_in[5];
    const float* Wv  = (const float*)d_in[6];
    const float* bv  = (const float*)d_in[7];
    const float* Wo  = (const float*)d_in[8];
    const float* bo  = (const float*)d_in[9];
    const float* W1  = (const float*)d_in[10];
    const float* b1  = (const float*)d_in[11];
    const float* W2  = (const float*)d_in[12];
    const float* b2  = (const float*)d_in[13];
    const float* G1  = (const float*)d_in[14];
    const float* Be1 = (const float*)d_in[15];
    const float* G2  = (const float*)d_in[16];
    const float* Be2 = (const float*)d_in[17];

    float *x, *q, *k, *v, *kv, *ks, *kvp, *ksp;
    __half *xh, *xl, *p2h, *p2l, *mh, *ml, *hh, *hl, *wth, *wtl;
    cudaGetSymbolAddress((void**)&x,   g_x);
    cudaGetSymbolAddress((void**)&q,   g_q);
    cudaGetSymbolAddress((void**)&k,   g_k);
    cudaGetSymbolAddress((void**)&v,   g_v);
    cudaGetSymbolAddress((void**)&kv,  g_kv);
    cudaGetSymbolAddress((void**)&ks,  g_ks);
    cudaGetSymbolAddress((void**)&kvp, g_kvp);
    cudaGetSymbolAddress((void**)&ksp, g_ksp);
    cudaGetSymbolAddress((void**)&xh,  g_xh);
    cudaGetSymbolAddress((void**)&xl,  g_xl);
    cudaGetSymbolAddress((void**)&p2h, g_p2h);
    cudaGetSymbolAddress((void**)&p2l, g_p2l);
    cudaGetSymbolAddress((void**)&mh,  g_mh);
    cudaGetSymbolAddress((void**)&ml,  g_ml);
    cudaGetSymbolAddress((void**)&hh,  g_hh);
    cudaGetSymbolAddress((void**)&hl,  g_hl);
    cudaGetSymbolAddress((void**)&wth, g_wth);
    cudaGetSymbolAddress((void**)&wtl, g_wtl);

    cudaFuncSetAttribute(gemm_hp, cudaFuncAttributeMaxDynamicSharedMemorySize, GSMEM);

    for (int li = 0; li < 4; li++) {
        size_t wo = (size_t)li * DMOD * DMOD;
        size_t wl = (size_t)li * WLAYER;
        wconv<<<dim3(8, 8),  256>>>(Wq + wo, wth + wl + 0,      wtl + wl + 0,      DMOD, DMOD);
        wconv<<<dim3(8, 8),  256>>>(Wk + wo, wth + wl + 65536,  wtl + wl + 65536,  DMOD, DMOD);
        wconv<<<dim3(8, 8),  256>>>(Wv + wo, wth + wl + 131072, wtl + wl + 131072, DMOD, DMOD);
        wconv<<<dim3(8, 8),  256>>>(Wo + wo, wth + wl + 196608, wtl + wl + 196608, DMOD, DMOD);
        wconv<<<dim3(16, 8), 256>>>(W1 + (size_t)li * DMOD * DFF, wth + wl + 262144, wtl + wl + 262144, DMOD, DFF);
        wconv<<<dim3(8, 16), 256>>>(W2 + (size_t)li * DFF * DMOD, wth + wl + 393216, wtl + wl + 393216, DFF, DMOD);
    }

    {
        dim3 pb(8 * 128, 8);
        posenc_kernel<<<pb, 256>>>(ref, src, x, xh, xl, p2h, p2l);
    }

    dim3 g256(2, MROWS / 128);
    dim3 g512(4, MROWS / 128);

    for (int li = 0; li < 4; li++) {
        size_t wl  = (size_t)li * WLAYER;
        size_t bo_ = (size_t)li * DMOD;
        size_t b1o = (size_t)li * DFF;
        const __half* sh = (li % 2 == 0) ? xh : p2h;
        const __half* sl = (li % 2 == 0) ? xl : p2l;

        gemm_hp<<<g256, 256, GSMEM>>>(xh, xl, wth + wl + 0,      wtl + wl + 0,      bq + bo_, q, 0, 0, MROWS, DMOD, DMOD, 1);
        gemm_hp<<<g256, 256, GSMEM>>>(sh, sl, wth + wl + 65536,  wtl + wl + 65536,  bk + bo_, k, 0, 0, MROWS, DMOD, DMOD, 1);
        gemm_hp<<<g256, 256, GSMEM>>>(sh, sl, wth + wl + 131072, wtl + wl + 131072, bv + bo_, v, 0, 0, MROWS, DMOD, DMOD, 0);

        kv_partial<<<BATCH * NHEAD * KVCH, 256>>>(k, v, kvp, ksp);
        kv_finalize<<<BATCH * NHEAD, 256>>>(kvp, ksp, kv, ks);
        attn_apply<<<BATCH * 32, 256>>>(q, kv, ks, mh, ml);

        gemm_hp<<<g256, 256, GSMEM>>>(mh, ml, wth + wl + 196608, wtl + wl + 196608, bo + bo_, v, 0, 0, MROWS, DMOD, DMOD, 0);
        ln_add<<<MROWS / 8, 256>>>(x, v, G1 + bo_, Be1 + bo_, x, xh, xl);

        gemm_hp<<<g512, 256, GSMEM>>>(xh, xl, wth + wl + 262144, wtl + wl + 262144, b1 + b1o, 0, hh, hl, MROWS, DFF, DMOD, 2);
        gemm_hp<<<g256, 256, GSMEM>>>(hh, hl, wth + wl + 393216, wtl + wl + 393216, b2 + bo_, q, 0, 0, MROWS, DMOD, DFF, 0);
        ln_add<<<MROWS / 8, 256>>>(x, q, G2 + bo_, Be2 + bo_, x, xh, xl);
    }

    {
        dim3 wb(8 * 128, 8);
        write_out<<<wb, 256>>>(x, (float*)d_out);
    }
}

// round 8
// speedup vs baseline: 2.1191x; 1.0335x over previous
#include <cuda_runtime.h>
#include <cuda_fp16.h>
#include <math.h>
#include <stdint.h>

#define BATCH 8
#define LSEQ  4096
#define DMOD  256
#define DFF   512
#define NHEAD 8
#define HDIM  32
#define MROWS (BATCH * LSEQ)
#define KVCH  16
#define STG   65536
#define GSMEM (3 * STG)
#define WLAYER 524288

__device__ float g_x [MROWS * DMOD];
__device__ float g_q [MROWS * DMOD];
__device__ float g_k [MROWS * DMOD];
__device__ float g_v [MROWS * DMOD];
__device__ float g_kv [BATCH * NHEAD * HDIM * HDIM];
__device__ float g_ks [BATCH * NHEAD * HDIM];
__device__ float g_kvp[BATCH * NHEAD * KVCH * HDIM * HDIM];
__device__ float g_ksp[BATCH * NHEAD * KVCH * HDIM];
__device__ __half g_xh [MROWS * DMOD];
__device__ __half g_xl [MROWS * DMOD];
__device__ __half g_p2h[MROWS * DMOD];
__device__ __half g_p2l[MROWS * DMOD];
__device__ __half g_mh [MROWS * DMOD];
__device__ __half g_ml [MROWS * DMOD];
__device__ __half g_hh [MROWS * DFF];
__device__ __half g_hl [MROWS * DFF];
__device__ __half g_wth[4 * WLAYER];
__device__ __half g_wtl[4 * WLAYER];

__device__ __forceinline__ uint32_t smem_u32(const void* p) {
    uint32_t a;
    asm("{ .reg .u64 t; cvta.to.shared.u64 t, %1; cvt.u32.u64 %0, t; }" : "=r"(a) : "l"(p));
    return a;
}
__device__ __forceinline__ uint32_t swz128(uint32_t off) { return off ^ ((off >> 3) & 0x70); }
__device__ __forceinline__ void cpa16(uint32_t dst, const void* src) {
    asm volatile("cp.async.cg.shared.global [%0], [%1], 16;" :: "r"(dst), "l"(src));
}
__device__ __forceinline__ void ldsm4(uint32_t* r, uint32_t a) {
    asm volatile("ldmatrix.sync.aligned.m8n8.x4.shared.b16 {%0,%1,%2,%3}, [%4];"
                 : "=r"(r[0]), "=r"(r[1]), "=r"(r[2]), "=r"(r[3]) : "r"(a));
}
__device__ __forceinline__ void mma16816(float* c, const uint32_t* a, uint32_t b0, uint32_t b1) {
    asm volatile(
        "mma.sync.aligned.m16n8k16.row.col.f32.f16.f16.f32 "
        "{%0,%1,%2,%3},{%4,%5,%6,%7},{%8,%9},{%0,%1,%2,%3};"
        : "+f"(c[0]), "+f"(c[1]), "+f"(c[2]), "+f"(c[3])
        : "r"(a[0]), "r"(a[1]), "r"(a[2]), "r"(a[3]), "r"(b0), "r"(b1));
}
__device__ __forceinline__ void split2h(float x, __half& h, __half& l) {
    h = __float2half_rn(x);
    l = __float2half_rn(x - __half2float(h));
}

__global__ void posenc_kernel(const float* __restrict__ ref, const float* __restrict__ src,
                              float* __restrict__ p1,
                              __half* __restrict__ p1h, __half* __restrict__ p1l,
                              __half* __restrict__ p2h, __half* __restrict__ p2l) {
    __shared__ float s[32][33];
    int img = blockIdx.y >> 2, n = blockIdx.y & 3;
    int ct = blockIdx.x >> 7, lt = blockIdx.x & 127;
    int c0 = ct * 32, l0 = lt * 32;
    int tid = threadIdx.x;
    const float* inp = (img == 0) ? ref : src;
#pragma unroll
    for (int p = 0; p < 4; p++) {
        int c = p * 8 + (tid >> 5), l = tid & 31;
        s[c][l] = inp[((size_t)n * DMOD + c0 + c) * LSEQ + l0 + l];
    }
    __syncthreads();
#pragma unroll
    for (int p = 0; p < 4; p++) {
        int l = p * 8 + (tid >> 5), c = tid & 31;
        int cg = c0 + c, lg = l0 + l;
        int ii = cg >> 2, jj = cg & 3;
        float dv = __expf(-(float)ii * (logf(10000.0f) / 64.0f));
        int w = lg & 63, hh = lg >> 6;
        float arg = (jj < 2 ? (float)w : (float)hh) * dv;
        float pe = (jj & 1) ? cosf(arg) : sinf(arg);
        float val = s[c][l] + pe;
        size_t o1 = ((size_t)(img * 4 + n) * LSEQ + lg) * DMOD + cg;
        size_t o2 = ((size_t)((1 - img) * 4 + n) * LSEQ + lg) * DMOD + cg;
        __half h, lo;
        split2h(val, h, lo);
        p1[o1] = val; p1h[o1] = h; p1l[o1] = lo;
        p2h[o2] = h;  p2l[o2] = lo;
    }
}

__global__ void wconv_all(const float* __restrict__ Wq, const float* __restrict__ Wk,
                          const float* __restrict__ Wv, const float* __restrict__ Wo,
                          const float* __restrict__ W1, const float* __restrict__ W2) {
    __shared__ float s[32][33];
    int li = blockIdx.x >> 9;
    int r  = blockIdx.x & 511;
    const float* src;
    size_t dsto;
    int K, N, n0, k0;
    if (r < 256) {
        int mat = r >> 6, t = r & 63;
        K = 256; N = 256;
        n0 = (t & 7) * 32; k0 = (t >> 3) * 32;
        const float* bases[4] = {Wq, Wk, Wv, Wo};
        src  = bases[mat] + (size_t)li * 65536;
        dsto = (size_t)li * WLAYER + (size_t)mat * 65536;
    } else if (r < 384) {
        int t = r - 256;
        K = 256; N = 512;
        n0 = (t & 15) * 32; k0 = (t >> 4) * 32;
        src  = W1 + (size_t)li * 131072;
        dsto = (size_t)li * WLAYER + 262144;
    } else {
        int t = r - 384;
        K = 512; N = 256;
        n0 = (t & 7) * 32; k0 = (t >> 3) * 32;
        src  = W2 + (size_t)li * 131072;
        dsto = (size_t)li * WLAYER + 393216;
    }
    int tid = threadIdx.x;
#pragma unroll
    for (int p = 0; p < 4; p++) {
        int kk = p * 8 + (tid >> 5), nn = tid & 31;
        s[kk][nn] = src[(size_t)(k0 + kk) * N + n0 + nn];
    }
    __syncthreads();
#pragma unroll
    for (int p = 0; p < 4; p++) {
        int nn = p * 8 + (tid >> 5), kk = tid & 31;
        float v = s[kk][nn];
        __half h, l;
        split2h(v, h, l);
        g_wth[dsto + (size_t)(n0 + nn) * K + k0 + kk] = h;
        g_wtl[dsto + (size_t)(n0 + nn) * K + k0 + kk] = l;
    }
}

__device__ __forceinline__ void load_stage(const __half* Ah, const __half* Al,
                                           const __half* Bh, const __half* Bl,
                                           int bm, int bn, int K, int k0,
                                           uint32_t sb, int tid) {
#pragma unroll
    for (int it = 0; it < 2; it++) {
        int c = tid + it * 512;
        int r = c >> 3, seg = c & 7;
        uint32_t d = swz128((uint32_t)(r * 128 + seg * 16));
        size_t ga = (size_t)(bm + r) * K + k0 + seg * 8;
        size_t gb = (size_t)(bn + r) * K + k0 + seg * 8;
        cpa16(sb + d,         Ah + ga);
        cpa16(sb + 16384 + d, Al + ga);
        cpa16(sb + 32768 + d, Bh + gb);
        cpa16(sb + 49152 + d, Bl + gb);
    }
    asm volatile("cp.async.commit_group;" ::: "memory");
}

__global__ __launch_bounds__(512, 1)
void gemm_hp(const __half* __restrict__ Ah, const __half* __restrict__ Al,
             const __half* __restrict__ Bh, const __half* __restrict__ Bl,
             const float* __restrict__ bias,
             float* __restrict__ Cf, __half* __restrict__ Ch, __half* __restrict__ Cl,
             int M, int N, int K, int mode) {
    extern __shared__ char smem[];
    uint32_t sb = smem_u32(smem);
    int tid = threadIdx.x, lane = tid & 31, warp = tid >> 5;
    int wm = warp >> 2, wn = warp & 3;
    int bm = blockIdx.y * 128, bn = blockIdx.x * 128;

    float acc[2][4][4];
#pragma unroll
    for (int i = 0; i < 2; i++)
#pragma unroll
        for (int j = 0; j < 4; j++)
#pragma unroll
            for (int r = 0; r < 4; r++) acc[i][j][r] = 0.0f;

    const int KT = K >> 6;
    load_stage(Ah, Al, Bh, Bl, bm, bn, K, 0, sb, tid);
    if (KT > 1) load_stage(Ah, Al, Bh, Bl, bm, bn, K, 64, sb + STG, tid);

    int lrow = (lane & 7) + ((lane >> 3) & 1) * 8;
    int kseg = (lane >> 4) * 16;

    for (int kt = 0; kt < KT; kt++) {
        if (kt + 1 < KT) asm volatile("cp.async.wait_group 1;" ::: "memory");
        else             asm volatile("cp.async.wait_group 0;" ::: "memory");
        __syncthreads();
        if (kt + 2 < KT)
            load_stage(Ah, Al, Bh, Bl, bm, bn, K, (kt + 2) << 6, sb + ((kt + 2) % 3) * STG, tid);

        uint32_t offA = sb + (kt % 3) * STG;
        uint32_t offAl = offA + 16384, offB = offA + 32768, offBl = offA + 49152;
#pragma unroll
        for (int kk = 0; kk < 4; kk++) {
            int kb = kk * 32 + kseg;
            uint32_t ah[2][4], al[2][4], bh[2][4], bl[2][4];
#pragma unroll
            for (int mt = 0; mt < 2; mt++) {
                uint32_t off = swz128((uint32_t)((wm * 32 + mt * 16 + lrow) * 128 + kb));
                ldsm4(ah[mt], offA  + off);
                ldsm4(al[mt], offAl + off);
            }
#pragma unroll
            for (int j = 0; j < 2; j++) {
                uint32_t off = swz128((uint32_t)((wn * 32 + j * 16 + lrow) * 128 + kb));
                ldsm4(bh[j], offB  + off);
                ldsm4(bl[j], offBl + off);
            }
#pragma unroll
            for (int mt = 0; mt < 2; mt++)
#pragma unroll
                for (int n8 = 0; n8 < 4; n8++) {
                    int j = n8 >> 1, s = n8 & 1;
                    mma16816(acc[mt][n8], ah[mt], bh[j][s], bh[j][2 + s]);
                    mma16816(acc[mt][n8], ah[mt], bl[j][s], bl[j][2 + s]);
                    mma16816(acc[mt][n8], al[mt], bh[j][s], bh[j][2 + s]);
                }
        }
        __syncthreads();
    }

    int gid = lane >> 2, tig = lane & 3;
#pragma unroll
    for (int n8 = 0; n8 < 4; n8++) {
        int col = bn + wn * 32 + n8 * 8 + tig * 2;
        float2 bv = *(const float2*)(bias + col);
#pragma unroll
        for (int mt = 0; mt < 2; mt++) {
            int row0 = bm + wm * 32 + mt * 16 + gid;
#pragma unroll
            for (int half = 0; half < 2; half++) {
                int row = row0 + half * 8;
                float v0 = acc[mt][n8][half * 2 + 0] + bv.x;
                float v1 = acc[mt][n8][half * 2 + 1] + bv.y;
                if (mode == 1) {
                    v0 = (v0 > 0.f) ? v0 + 1.f : __expf(v0);
                    v1 = (v1 > 0.f) ? v1 + 1.f : __expf(v1);
                } else if (mode == 2) {
                    v0 = fmaxf(v0, 0.f);
                    v1 = fmaxf(v1, 0.f);
                }
                if (mode == 2) {
                    __half h0, l0, h1, l1;
                    split2h(v0, h0, l0);
                    split2h(v1, h1, l1);
                    *(__half2*)(Ch + (size_t)row * N + col) = __halves2half2(h0, h1);
                    *(__half2*)(Cl + (size_t)row * N + col) = __halves2half2(l0, l1);
                } else {
                    *(float2*)(Cf + (size_t)row * N + col) = make_float2(v0, v1);
                }
            }
        }
    }
}

__global__ void kv_partial(const float* __restrict__ Kin, const float* __restrict__ Vin,
                           float* __restrict__ KVp, float* __restrict__ Ksp) {
    int blk = blockIdx.x;
    int bh = blk >> 4, ch = blk & (KVCH - 1);
    int b = bh >> 3, h = bh & 7;
    int tid = threadIdx.x;
    __shared__ float Ks[32][36];
    __shared__ float Vs[32][32];
    int m = tid >> 3, d0 = (tid & 7) * 4;
    float acc[4] = {0.f, 0.f, 0.f, 0.f};
    float ks[4]  = {0.f, 0.f, 0.f, 0.f};
    int lr = tid >> 3, lc = (tid & 7) * 4;
    int lbeg = ch * (LSEQ / KVCH), lend = lbeg + (LSEQ / KVCH);
    for (int l0 = lbeg; l0 < lend; l0 += 32) {
        size_t base = ((size_t)(b * LSEQ + l0 + lr)) * DMOD + h * HDIM + lc;
        float4 kv4 = *(const float4*)(Kin + base);
        float4 vv4 = *(const float4*)(Vin + base);
        Ks[lr][lc + 0] = kv4.x; Ks[lr][lc + 1] = kv4.y;
        Ks[lr][lc + 2] = kv4.z; Ks[lr][lc + 3] = kv4.w;
        *(float4*)&Vs[lr][lc] = vv4;
        __syncthreads();
#pragma unroll 8
        for (int r = 0; r < 32; r++) {
            float vm = Vs[r][m];
#pragma unroll
            for (int j = 0; j < 4; j++) acc[j] = fmaf(vm, Ks[r][d0 + j], acc[j]);
            if (m == 0) {
#pragma unroll
                for (int j = 0; j < 4; j++) ks[j] += Ks[r][d0 + j];
            }
        }
        __syncthreads();
    }
    size_t obase = ((size_t)blk * HDIM + m) * HDIM + d0;
#pragma unroll
    for (int j = 0; j < 4; j++) KVp[obase + j] = acc[j];
    if (m == 0) {
#pragma unroll
        for (int j = 0; j < 4; j++) Ksp[blk * HDIM + d0 + j] = ks[j];
    }
}

__global__ void kv_finalize(const float* __restrict__ KVp, const float* __restrict__ Ksp,
                            float* __restrict__ KV, float* __restrict__ Ksum) {
    int bh = blockIdx.x, tid = threadIdx.x;
#pragma unroll
    for (int o = 0; o < 4; o++) {
        int idx = tid + o * 256;
        float s = 0.f;
#pragma unroll
        for (int c = 0; c < KVCH; c++)
            s += KVp[((size_t)(bh * KVCH + c)) * (HDIM * HDIM) + idx];
        KV[(size_t)bh * (HDIM * HDIM) + idx] = s;
    }
    if (tid < HDIM) {
        float s = 0.f;
#pragma unroll
        for (int c = 0; c < KVCH; c++)
            s += Ksp[(bh * KVCH + c) * HDIM + tid];
        Ksum[bh * HDIM + tid] = s;
    }
}

__global__ void attn_apply(const float* __restrict__ Q, const float* __restrict__ KV,
                           const float* __restrict__ Ksum,
                           __half* __restrict__ Mh, __half* __restrict__ Ml) {
    int blk = blockIdx.x;
    int b = blk >> 5, lt = (blk & 31) * 128;
    int tid = threadIdx.x;
    __shared__ float KVs[NHEAD * HDIM * 33];
    __shared__ float Ksums[NHEAD * HDIM];
    for (int i = tid; i < NHEAD * HDIM * HDIM; i += 256) {
        int h = i >> 10, m = (i >> 5) & 31, d = i & 31;
        KVs[(h * HDIM + m) * 33 + d] = KV[((size_t)(b * NHEAD + h) * HDIM + m) * HDIM + d];
    }
    for (int i = tid; i < NHEAD * HDIM; i += 256)
        Ksums[i] = Ksum[b * NHEAD * HDIM + i];
    __syncthreads();
    int h = tid >> 5, m = tid & 31;
    const float* kvrow = &KVs[(h * HDIM + m) * 33];
    const float* ksr   = &Ksums[h * HDIM];
    for (int r = 0; r < 128; r++) {
        int l = lt + r;
        const float* q = Q + ((size_t)(b * LSEQ + l)) * DMOD + h * HDIM;
        float num = 0.f, den = 0.f;
#pragma unroll
        for (int d = 0; d < HDIM; d += 4) {
            float4 qv = *(const float4*)(q + d);
            num = fmaf(qv.x, kvrow[d],     num);
            num = fmaf(qv.y, kvrow[d + 1], num);
            num = fmaf(qv.z, kvrow[d + 2], num);
            num = fmaf(qv.w, kvrow[d + 3], num);
            den = fmaf(qv.x, ksr[d],     den);
            den = fmaf(qv.y, ksr[d + 1], den);
            den = fmaf(qv.z, ksr[d + 2], den);
            den = fmaf(qv.w, ksr[d + 3], den);
        }
        float o = num / (den + 1e-6f);
        __half hh, ll;
        split2h(o, hh, ll);
        size_t oi = ((size_t)(b * LSEQ + l)) * DMOD + tid;
        Mh[oi] = hh; Ml[oi] = ll;
    }
}

__global__ void ln_add(const float* __restrict__ A, const float* __restrict__ Bt,
                       const float* __restrict__ gamma, const float* __restrict__ beta,
                       float* __restrict__ Out,
                       __half* __restrict__ Oh, __half* __restrict__ Ol) {
    int row  = blockIdx.x * 8 + (threadIdx.x >> 5);
    int lane = threadIdx.x & 31;
    const float* a  = A  + (size_t)row * DMOD;
    const float* bb = Bt + (size_t)row * DMOD;
    int c0 = lane * 4, c1 = 128 + lane * 4;
    float4 x0 = *(const float4*)(a + c0);
    float4 x1 = *(const float4*)(a + c1);
    float4 y0 = *(const float4*)(bb + c0);
    float4 y1 = *(const float4*)(bb + c1);
    float v[8];
    v[0] = x0.x + y0.x; v[1] = x0.y + y0.y; v[2] = x0.z + y0.z; v[3] = x0.w + y0.w;
    v[4] = x1.x + y1.x; v[5] = x1.y + y1.y; v[6] = x1.z + y1.z; v[7] = x1.w + y1.w;
    float s = 0.f;
#pragma unroll
    for (int i = 0; i < 8; i++) s += v[i];
#pragma unroll
    for (int o = 16; o > 0; o >>= 1) s += __shfl_xor_sync(0xffffffffu, s, o);
    float mean = s * (1.0f / 256.0f);
    float qv = 0.f;
#pragma unroll
    for (int i = 0; i < 8; i++) { float d = v[i] - mean; qv += d * d; }
#pragma unroll
    for (int o = 16; o > 0; o >>= 1) qv += __shfl_xor_sync(0xffffffffu, qv, o);
    float inv = rsqrtf(qv * (1.0f / 256.0f) + 1e-5f);
    float o8[8];
#pragma unroll
    for (int i = 0; i < 4; i++)
        o8[i] = (v[i] - mean) * inv * gamma[c0 + i] + beta[c0 + i];
#pragma unroll
    for (int i = 0; i < 4; i++)
        o8[4 + i] = (v[4 + i] - mean) * inv * gamma[c1 + i] + beta[c1 + i];
    float* op = Out + (size_t)row * DMOD;
    *(float4*)(op + c0) = *(float4*)(o8);
    *(float4*)(op + c1) = *(float4*)(o8 + 4);
    union { __half b[4]; uint2 u; } h0, l0, h1, l1;
#pragma unroll
    for (int i = 0; i < 4; i++) split2h(o8[i],     h0.b[i], l0.b[i]);
#pragma unroll
    for (int i = 0; i < 4; i++) split2h(o8[4 + i], h1.b[i], l1.b[i]);
    *(uint2*)(Oh + (size_t)row * DMOD + c0) = h0.u;
    *(uint2*)(Ol + (size_t)row * DMOD + c0) = l0.u;
    *(uint2*)(Oh + (size_t)row * DMOD + c1) = h1.u;
    *(uint2*)(Ol + (size_t)row * DMOD + c1) = l1.u;
}

__global__ void write_out(const float* __restrict__ X, float* __restrict__ out) {
    __shared__ float s[32][33];
    int n  = blockIdx.y;
    int ct = blockIdx.x >> 7, lt = blockIdx.x & 127;
    int c0 = ct * 32, l0 = lt * 32;
    int tid = threadIdx.x;
#pragma unroll
    for (int p = 0; p < 4; p++) {
        int l = p * 8 + (tid >> 5), c = tid & 31;
        s[l][c] = X[((size_t)n * LSEQ + l0 + l) * DMOD + c0 + c];
    }
    __syncthreads();
#pragma unroll
    for (int p = 0; p < 4; p++) {
        int c = p * 8 + (tid >> 5), l = tid & 31;
        out[((size_t)n * DMOD + c0 + c) * LSEQ + l0 + l] = s[l][c];
    }
}

extern "C" void kernel_launch(void* const* d_in, const int* in_sizes, int n_in,
                              void* d_out, int out_size) {
    const float* ref = (const float*)d_in[0];
    const float* src = (const float*)d_in[1];
    const float* Wq  = (const float*)d_in[2];
    const float* bq  = (const float*)d_in[3];
    const float* Wk  = (const float*)d_in[4];
    const float* bk  = (const float*)d_in[5];
    const float* Wv  = (const float*)d_in[6];
    const float* bv  = (const float*)d_in[7];
    const float* Wo  = (const float*)d_in[8];
    const float* bo  = (const float*)d_in[9];
    const float* W1  = (const float*)d_in[10];
    const float* b1  = (const float*)d_in[11];
    const float* W2  = (const float*)d_in[12];
    const float* b2  = (const float*)d_in[13];
    const float* G1  = (const float*)d_in[14];
    const float* Be1 = (const float*)d_in[15];
    const float* G2  = (const float*)d_in[16];
    const float* Be2 = (const float*)d_in[17];

    float *x, *q, *k, *v, *kv, *ks, *kvp, *ksp;
    __half *xh, *xl, *p2h, *p2l, *mh, *ml, *hh, *hl, *wth, *wtl;
    cudaGetSymbolAddress((void**)&x,   g_x);
    cudaGetSymbolAddress((void**)&q,   g_q);
    cudaGetSymbolAddress((void**)&k,   g_k);
    cudaGetSymbolAddress((void**)&v,   g_v);
    cudaGetSymbolAddress((void**)&kv,  g_kv);
    cudaGetSymbolAddress((void**)&ks,  g_ks);
    cudaGetSymbolAddress((void**)&kvp, g_kvp);
    cudaGetSymbolAddress((void**)&ksp, g_ksp);
    cudaGetSymbolAddress((void**)&xh,  g_xh);
    cudaGetSymbolAddress((void**)&xl,  g_xl);
    cudaGetSymbolAddress((void**)&p2h, g_p2h);
    cudaGetSymbolAddress((void**)&p2l, g_p2l);
    cudaGetSymbolAddress((void**)&mh,  g_mh);
    cudaGetSymbolAddress((void**)&ml,  g_ml);
    cudaGetSymbolAddress((void**)&hh,  g_hh);
    cudaGetSymbolAddress((void**)&hl,  g_hl);
    cudaGetSymbolAddress((void**)&wth, g_wth);
    cudaGetSymbolAddress((void**)&wtl, g_wtl);

    cudaFuncSetAttribute(gemm_hp, cudaFuncAttributeMaxDynamicSharedMemorySize, GSMEM);

    wconv_all<<<2048, 256>>>(Wq, Wk, Wv, Wo, W1, W2);
    {
        dim3 pb(8 * 128, 8);
        posenc_kernel<<<pb, 256>>>(ref, src, x, xh, xl, p2h, p2l);
    }

    dim3 g256(2, MROWS / 128);
    dim3 g512(4, MROWS / 128);

    for (int li = 0; li < 4; li++) {
        size_t wl  = (size_t)li * WLAYER;
        size_t bo_ = (size_t)li * DMOD;
        size_t b1o = (size_t)li * DFF;
        const __half* sh = (li % 2 == 0) ? xh : p2h;
        const __half* sl = (li % 2 == 0) ? xl : p2l;

        gemm_hp<<<g256, 512, GSMEM>>>(xh, xl, wth + wl + 0,      wtl + wl + 0,      bq + bo_, q, 0, 0, MROWS, DMOD, DMOD, 1);
        gemm_hp<<<g256, 512, GSMEM>>>(sh, sl, wth + wl + 65536,  wtl + wl + 65536,  bk + bo_, k, 0, 0, MROWS, DMOD, DMOD, 1);
        gemm_hp<<<g256, 512, GSMEM>>>(sh, sl, wth + wl + 131072, wtl + wl + 131072, bv + bo_, v, 0, 0, MROWS, DMOD, DMOD, 0);

        kv_partial<<<BATCH * NHEAD * KVCH, 256>>>(k, v, kvp, ksp);
        kv_finalize<<<BATCH * NHEAD, 256>>>(kvp, ksp, kv, ks);
        attn_apply<<<BATCH * 32, 256>>>(q, kv, ks, mh, ml);

        gemm_hp<<<g256, 512, GSMEM>>>(mh, ml, wth + wl + 196608, wtl + wl + 196608, bo + bo_, v, 0, 0, MROWS, DMOD, DMOD, 0);
        ln_add<<<MROWS / 8, 256>>>(x, v, G1 + bo_, Be1 + bo_, x, xh, xl);

        gemm_hp<<<g512, 512, GSMEM>>>(xh, xl, wth + wl + 262144, wtl + wl + 262144, b1 + b1o, 0, hh, hl, MROWS, DFF, DMOD, 2);
        gemm_hp<<<g256, 512, GSMEM>>>(hh, hl, wth + wl + 393216, wtl + wl + 393216, b2 + bo_, q, 0, 0, MROWS, DMOD, DFF, 0);
        ln_add<<<MROWS / 8, 256>>>(x, q, G2 + bo_, Be2 + bo_, x, xh, xl);
    }

    {
        dim3 wb(8 * 128, 8);
        write_out<<<wb, 256>>>(x, (float*)d_out);
    }
}